// round 2
// baseline (speedup 1.0000x reference)
#include <cuda_runtime.h>
#include <math.h>

// Problem constants
constexpr int Bz   = 8;
constexpr int Nq   = 256;
constexpr int Mc   = 1024;
constexpr int Cd   = 1024;
constexpr int Hh   = 16;
constexpr int Dd   = 64;

// Scratch (allowed as __device__ globals)
__device__ float g_Q[Bz * Nq * Cd];   // 8 MB
__device__ float g_K[Bz * Mc * Cd];   // 32 MB
__device__ float g_V[Bz * Mc * Cd];   // 32 MB
__device__ float g_O[Bz * Nq * Cd];   // 8 MB

// ---------------------------------------------------------------------------
// SGEMM: C[Ma,Nb] = A[Ma,K] * B[Nb,K]^T (+ bias), 128x128x8 tiles, 8x8 micro
// ---------------------------------------------------------------------------
__global__ __launch_bounds__(256, 2)
void sgemm_nt_128(const float* __restrict__ A, const float* __restrict__ Bw,
                  const float* __restrict__ bias, float* __restrict__ Cc,
                  int Ma, int Nb, int K) {
    __shared__ float As[8][128];
    __shared__ float Bs[8][128];

    const int tid  = threadIdx.x;
    const int brow = blockIdx.y * 128;
    const int bcol = blockIdx.x * 128;
    const int lr   = tid >> 1;          // 0..127
    const int lk   = (tid & 1) * 4;     // 0 or 4
    const float* Ap = A  + (size_t)(brow + lr) * K + lk;
    const float* Bp = Bw + (size_t)(bcol + lr) * K + lk;
    const int ty = tid >> 4;            // 0..15
    const int tx = tid & 15;            // 0..15

    float acc[8][8];
#pragma unroll
    for (int i = 0; i < 8; i++)
#pragma unroll
        for (int j = 0; j < 8; j++) acc[i][j] = 0.f;

    for (int k0 = 0; k0 < K; k0 += 8) {
        float4 av = *(const float4*)(Ap + k0);
        float4 bv = *(const float4*)(Bp + k0);
        As[lk + 0][lr] = av.x; As[lk + 1][lr] = av.y;
        As[lk + 2][lr] = av.z; As[lk + 3][lr] = av.w;
        Bs[lk + 0][lr] = bv.x; Bs[lk + 1][lr] = bv.y;
        Bs[lk + 2][lr] = bv.z; Bs[lk + 3][lr] = bv.w;
        __syncthreads();
#pragma unroll
        for (int kk = 0; kk < 8; kk++) {
            float a[8], b[8];
            *(float4*)&a[0] = *(const float4*)&As[kk][ty * 8];
            *(float4*)&a[4] = *(const float4*)&As[kk][ty * 8 + 4];
            *(float4*)&b[0] = *(const float4*)&Bs[kk][tx * 8];
            *(float4*)&b[4] = *(const float4*)&Bs[kk][tx * 8 + 4];
#pragma unroll
            for (int i = 0; i < 8; i++)
#pragma unroll
                for (int j = 0; j < 8; j++)
                    acc[i][j] = fmaf(a[i], b[j], acc[i][j]);
        }
        __syncthreads();
    }

#pragma unroll
    for (int i = 0; i < 8; i++) {
        const int row = brow + ty * 8 + i;
        float* cp = Cc + (size_t)row * Nb + bcol + tx * 8;
        if (bias != nullptr) {
            const float* bpp = bias + bcol + tx * 8;
#pragma unroll
            for (int j = 0; j < 8; j++) cp[j] = acc[i][j] + bpp[j];
        } else {
            *(float4*)(cp)     = make_float4(acc[i][0], acc[i][1], acc[i][2], acc[i][3]);
            *(float4*)(cp + 4) = make_float4(acc[i][4], acc[i][5], acc[i][6], acc[i][7]);
        }
    }
}

// ---------------------------------------------------------------------------
// LayerNorm over contiguous 64-element groups (one warp per group)
// ---------------------------------------------------------------------------
__global__ void ln64_kernel(float* __restrict__ X, const float* __restrict__ gamma,
                            const float* __restrict__ beta, int ngroups) {
    const int warp = (blockIdx.x * blockDim.x + threadIdx.x) >> 5;
    const int lane = threadIdx.x & 31;
    if (warp >= ngroups) return;
    float* x = X + (size_t)warp * 64;
    float x0 = x[lane];
    float x1 = x[lane + 32];
    float s  = x0 + x1;
    float sq = x0 * x0 + x1 * x1;
#pragma unroll
    for (int o = 16; o > 0; o >>= 1) {
        s  += __shfl_xor_sync(0xFFFFFFFFu, s, o);
        sq += __shfl_xor_sync(0xFFFFFFFFu, sq, o);
    }
    const float mean = s * (1.f / 64.f);
    const float var  = sq * (1.f / 64.f) - mean * mean;
    const float rstd = rsqrtf(var + 1e-5f);
    x[lane]      = (x0 - mean) * rstd * gamma[lane]      + beta[lane];
    x[lane + 32] = (x1 - mean) * rstd * gamma[lane + 32] + beta[lane + 32];
}

// ---------------------------------------------------------------------------
// Scores: attn_raw[bh,n,m] = scale * q.k (masked). 64x64 tile, K-dim=64.
// grid: (Mc/64, Nq/64, Bz*Hh), block 256
// ---------------------------------------------------------------------------
__global__ __launch_bounds__(256)
void scores_kernel(const float* __restrict__ Q, const float* __restrict__ Kc,
                   const int* __restrict__ mask, float* __restrict__ attn) {
    const int bh = blockIdx.z;
    const int b  = bh >> 4;
    const int h  = bh & 15;
    const int n0 = blockIdx.y * 64;
    const int m0 = blockIdx.x * 64;

    __shared__ float Qs[64][68];   // [d][n]
    __shared__ float Ks[64][68];   // [d][m]

    const int tid = threadIdx.x;
    {
        const int r  = tid >> 2;            // 0..63
        const int d0 = (tid & 3) * 16;
        const float* qp = Q  + (size_t)(b * Nq + n0 + r) * Cd + h * 64 + d0;
        const float* kp = Kc + (size_t)(b * Mc + m0 + r) * Cd + h * 64 + d0;
#pragma unroll
        for (int v = 0; v < 4; v++) {
            float4 qv = *(const float4*)(qp + v * 4);
            float4 kv = *(const float4*)(kp + v * 4);
            Qs[d0 + v * 4 + 0][r] = qv.x; Qs[d0 + v * 4 + 1][r] = qv.y;
            Qs[d0 + v * 4 + 2][r] = qv.z; Qs[d0 + v * 4 + 3][r] = qv.w;
            Ks[d0 + v * 4 + 0][r] = kv.x; Ks[d0 + v * 4 + 1][r] = kv.y;
            Ks[d0 + v * 4 + 2][r] = kv.z; Ks[d0 + v * 4 + 3][r] = kv.w;
        }
    }
    __syncthreads();

    const int ty = tid >> 4, tx = tid & 15;
    float acc[4][4];
#pragma unroll
    for (int i = 0; i < 4; i++)
#pragma unroll
        for (int j = 0; j < 4; j++) acc[i][j] = 0.f;

#pragma unroll 16
    for (int d = 0; d < 64; d++) {
        float4 a = *(const float4*)&Qs[d][ty * 4];
        float4 c = *(const float4*)&Ks[d][tx * 4];
        float av[4] = {a.x, a.y, a.z, a.w};
        float bv[4] = {c.x, c.y, c.z, c.w};
#pragma unroll
        for (int i = 0; i < 4; i++)
#pragma unroll
            for (int j = 0; j < 4; j++)
                acc[i][j] = fmaf(av[i], bv[j], acc[i][j]);
    }

    const float scale = 0.125f;  // D^-0.5
#pragma unroll
    for (int j = 0; j < 4; j++) {
        const int m = m0 + tx * 4 + j;
        const bool ok = mask[b * Mc + m] != 0;
#pragma unroll
        for (int i = 0; i < 4; i++) {
            const int n = n0 + ty * 4 + i;
            float sv = acc[i][j] * scale;
            if (!ok) sv = -1e30f;
            attn[((size_t)bh * Nq + n) * Mc + m] = sv;
        }
    }
}

// ---------------------------------------------------------------------------
// Softmax in place over rows of length 1024 (one warp per row)
// ---------------------------------------------------------------------------
__global__ void softmax_kernel(float* __restrict__ attn, int rows) {
    const int row  = (blockIdx.x * blockDim.x + threadIdx.x) >> 5;
    const int lane = threadIdx.x & 31;
    if (row >= rows) return;
    float* p = attn + (size_t)row * 1024;

    float4 v[8];
    float mx = -1e30f;
#pragma unroll
    for (int i = 0; i < 8; i++) {
        v[i] = *(const float4*)(p + (size_t)(i * 32 + lane) * 4);
        mx = fmaxf(mx, fmaxf(fmaxf(v[i].x, v[i].y), fmaxf(v[i].z, v[i].w)));
    }
#pragma unroll
    for (int o = 16; o > 0; o >>= 1) mx = fmaxf(mx, __shfl_xor_sync(0xFFFFFFFFu, mx, o));

    float sum = 0.f;
#pragma unroll
    for (int i = 0; i < 8; i++) {
        v[i].x = __expf(v[i].x - mx);
        v[i].y = __expf(v[i].y - mx);
        v[i].z = __expf(v[i].z - mx);
        v[i].w = __expf(v[i].w - mx);
        sum += v[i].x + v[i].y + v[i].z + v[i].w;
    }
#pragma unroll
    for (int o = 16; o > 0; o >>= 1) sum += __shfl_xor_sync(0xFFFFFFFFu, sum, o);
    const float inv = 1.f / sum;

#pragma unroll
    for (int i = 0; i < 8; i++) {
        v[i].x *= inv; v[i].y *= inv; v[i].z *= inv; v[i].w *= inv;
        *(float4*)(p + (size_t)(i * 32 + lane) * 4) = v[i];
    }
}

// ---------------------------------------------------------------------------
// AV: O[b,n,h*64+d] = sum_m attn[bh,n,m] * V[b,m,h*64+d]
// grid: (Nq/64, Bz*Hh), block 256. 64n x 64d tile, 32-wide m chunks.
// ---------------------------------------------------------------------------
__global__ __launch_bounds__(256)
void av_kernel(const float* __restrict__ attn, const float* __restrict__ V,
               float* __restrict__ O) {
    const int bh = blockIdx.y;
    const int b  = bh >> 4;
    const int h  = bh & 15;
    const int n0 = blockIdx.x * 64;

    __shared__ float Asm[32][68];   // [m][n]
    __shared__ float Vs[32][64];    // [m][d]

    const int tid = threadIdx.x;
    const int ty = tid >> 4, tx = tid & 15;
    float acc[4][4];
#pragma unroll
    for (int i = 0; i < 4; i++)
#pragma unroll
        for (int j = 0; j < 4; j++) acc[i][j] = 0.f;

    for (int mc = 0; mc < Mc; mc += 32) {
        {
            const int n  = tid >> 2;            // 0..63
            const int ml = (tid & 3) * 8;
            const float* ap = attn + ((size_t)bh * Nq + n0 + n) * Mc + mc + ml;
            float4 a0 = *(const float4*)ap;
            float4 a1 = *(const float4*)(ap + 4);
            Asm[ml + 0][n] = a0.x; Asm[ml + 1][n] = a0.y;
            Asm[ml + 2][n] = a0.z; Asm[ml + 3][n] = a0.w;
            Asm[ml + 4][n] = a1.x; Asm[ml + 5][n] = a1.y;
            Asm[ml + 6][n] = a1.z; Asm[ml + 7][n] = a1.w;

            const int m  = tid >> 3;            // 0..31
            const int dl = (tid & 7) * 8;
            const float* vp = V + (size_t)(b * Mc + mc + m) * Cd + h * 64 + dl;
            *(float4*)&Vs[m][dl]     = *(const float4*)vp;
            *(float4*)&Vs[m][dl + 4] = *(const float4*)(vp + 4);
        }
        __syncthreads();
#pragma unroll
        for (int mm = 0; mm < 32; mm++) {
            float4 a = *(const float4*)&Asm[mm][ty * 4];
            float4 c = *(const float4*)&Vs[mm][tx * 4];
            float av[4] = {a.x, a.y, a.z, a.w};
            float bv[4] = {c.x, c.y, c.z, c.w};
#pragma unroll
            for (int i = 0; i < 4; i++)
#pragma unroll
                for (int j = 0; j < 4; j++)
                    acc[i][j] = fmaf(av[i], bv[j], acc[i][j]);
        }
        __syncthreads();
    }

#pragma unroll
    for (int i = 0; i < 4; i++) {
        const int n = n0 + ty * 4 + i;
        float* op = O + (size_t)(b * Nq + n) * Cd + h * 64 + tx * 4;
        *(float4*)op = make_float4(acc[i][0], acc[i][1], acc[i][2], acc[i][3]);
    }
}

// ---------------------------------------------------------------------------
// Launch
// ---------------------------------------------------------------------------
extern "C" void kernel_launch(void* const* d_in, const int* in_sizes, int n_in,
                              void* d_out, int out_size) {
    const float* query   = (const float*)d_in[0];
    const float* context = (const float*)d_in[1];
    const int*   mask    = (const int*)d_in[2];     // bool canonicalized to int32
    const float* Wq      = (const float*)d_in[3];
    const float* Wk      = (const float*)d_in[4];
    const float* Wv      = (const float*)d_in[5];
    const float* qg      = (const float*)d_in[6];
    const float* qb      = (const float*)d_in[7];
    const float* kg      = (const float*)d_in[8];
    const float* kb      = (const float*)d_in[9];
    const float* Wp      = (const float*)d_in[10];
    const float* bp      = (const float*)d_in[11];

    float* out  = (float*)d_out;                       // [B,N,C]
    float* attn = out + (size_t)Bz * Nq * Cd;          // [B,H,N,M]

    float *Qp, *Kp, *Vp, *Op;
    cudaGetSymbolAddress((void**)&Qp, g_Q);
    cudaGetSymbolAddress((void**)&Kp, g_K);
    cudaGetSymbolAddress((void**)&Vp, g_V);
    cudaGetSymbolAddress((void**)&Op, g_O);

    // Projections
    {
        dim3 gq(Cd / 128, (Bz * Nq) / 128);            // 8 x 16
        sgemm_nt_128<<<gq, 256>>>(query, Wq, nullptr, Qp, Bz * Nq, Cd, Cd);
        dim3 gk(Cd / 128, (Bz * Mc) / 128);            // 8 x 64
        sgemm_nt_128<<<gk, 256>>>(context, Wk, nullptr, Kp, Bz * Mc, Cd, Cd);
        sgemm_nt_128<<<gk, 256>>>(context, Wv, nullptr, Vp, Bz * Mc, Cd, Cd);
    }

    // LayerNorm q, k (per-head 64-element groups)
    {
        const int gq = Bz * Nq * Hh;   // 32768 groups
        const int gk = Bz * Mc * Hh;   // 131072 groups
        ln64_kernel<<<(gq * 32 + 255) / 256, 256>>>(Qp, qg, qb, gq);
        ln64_kernel<<<(gk * 32 + 255) / 256, 256>>>(Kp, kg, kb, gk);
    }

    // Scores (+scale, +mask)
    {
        dim3 gs(Mc / 64, Nq / 64, Bz * Hh);            // 16 x 4 x 128
        scores_kernel<<<gs, 256>>>(Qp, Kp, mask, attn);
    }

    // Softmax in place
    {
        const int rows = Bz * Hh * Nq;                 // 32768
        softmax_kernel<<<(rows * 32 + 255) / 256, 256>>>(attn, rows);
    }

    // attn @ V
    {
        dim3 ga(Nq / 64, Bz * Hh);                     // 4 x 128
        av_kernel<<<ga, 256>>>(attn, Vp, Op);
    }

    // Output projection + bias
    {
        dim3 go(Cd / 128, (Bz * Nq) / 128);            // 8 x 16
        sgemm_nt_128<<<go, 256>>>(Op, Wp, bp, out, Bz * Nq, Cd, Cd);
    }
}

// round 3
// speedup vs baseline: 1.3110x; 1.3110x over previous
#include <cuda_runtime.h>
#include <mma.h>
#include <math.h>

using namespace nvcuda;

// Problem constants
constexpr int Bz = 8;
constexpr int Nq = 256;
constexpr int Mc = 1024;
constexpr int Cd = 1024;
constexpr int Hh = 16;

// Scratch
__device__ float g_Q[Bz * Nq * Cd];   // 8 MB
__device__ float g_K[Bz * Mc * Cd];   // 32 MB
__device__ float g_V[Bz * Mc * Cd];   // 32 MB
__device__ float g_O[Bz * Nq * Cd];   // 8 MB

// ---------------------------------------------------------------------------
// TF32 tensor-core GEMM: C[Ma,Nb] = A[Ma,K] * B[Nb,K]^T (+ bias)
// 128x128 CTA tile, 8 warps, warp tile 64x32 (4x2 wmma 16x16x8 frags), k=32.
// ---------------------------------------------------------------------------
__global__ __launch_bounds__(256)
void gemm_tf32_128(const float* __restrict__ A, const float* __restrict__ Bw,
                   const float* __restrict__ bias, float* __restrict__ Cc,
                   int Ma, int Nb, int K) {
    __shared__ float As[128][40];
    __shared__ float Bs[128][40];

    const int tid  = threadIdx.x;
    const int brow = blockIdx.y * 128;
    const int bcol = blockIdx.x * 128;
    const int wid  = tid >> 5;
    const int wm   = (wid & 1) * 64;    // warp m offset
    const int wn   = (wid >> 1) * 32;   // warp n offset

    wmma::fragment<wmma::accumulator, 16, 16, 8, float> cf[4][2];

    if (bias != nullptr) {
        // Build a 16x132 bias tile (rows replicated) in As scratch, preload C frags.
        float* bt = &As[0][0];  // 128*40 = 5120 floats >= 16*132
        for (int i = tid; i < 16 * 132; i += 256) {
            int col = i % 132;
            bt[i] = (col < 128) ? bias[bcol + col] : 0.f;
        }
        __syncthreads();
#pragma unroll
        for (int mt = 0; mt < 4; mt++)
#pragma unroll
            for (int nt = 0; nt < 2; nt++)
                wmma::load_matrix_sync(cf[mt][nt], bt + wn + nt * 16, 132,
                                       wmma::mem_row_major);
        __syncthreads();
    } else {
#pragma unroll
        for (int mt = 0; mt < 4; mt++)
#pragma unroll
            for (int nt = 0; nt < 2; nt++)
                wmma::fill_fragment(cf[mt][nt], 0.f);
    }

    const int lr = tid >> 1;            // 0..127
    const int lk = (tid & 1) * 16;      // 0 or 16
    const float* Ap = A  + (size_t)(brow + lr) * K + lk;
    const float* Bp = Bw + (size_t)(bcol + lr) * K + lk;

    float4 ra[4], rb[4];

    // prologue: load tile 0
#pragma unroll
    for (int v = 0; v < 4; v++) {
        ra[v] = *(const float4*)(Ap + v * 4);
        rb[v] = *(const float4*)(Bp + v * 4);
    }
#pragma unroll
    for (int v = 0; v < 4; v++) {
        As[lr][lk + v * 4 + 0] = wmma::__float_to_tf32(ra[v].x);
        As[lr][lk + v * 4 + 1] = wmma::__float_to_tf32(ra[v].y);
        As[lr][lk + v * 4 + 2] = wmma::__float_to_tf32(ra[v].z);
        As[lr][lk + v * 4 + 3] = wmma::__float_to_tf32(ra[v].w);
        Bs[lr][lk + v * 4 + 0] = wmma::__float_to_tf32(rb[v].x);
        Bs[lr][lk + v * 4 + 1] = wmma::__float_to_tf32(rb[v].y);
        Bs[lr][lk + v * 4 + 2] = wmma::__float_to_tf32(rb[v].z);
        Bs[lr][lk + v * 4 + 3] = wmma::__float_to_tf32(rb[v].w);
    }
    __syncthreads();

    const int niter = K / 32;
    for (int t = 0; t < niter; t++) {
        if (t + 1 < niter) {
            const int k0 = (t + 1) * 32;
#pragma unroll
            for (int v = 0; v < 4; v++) {
                ra[v] = *(const float4*)(Ap + k0 + v * 4);
                rb[v] = *(const float4*)(Bp + k0 + v * 4);
            }
        }

#pragma unroll
        for (int ks = 0; ks < 4; ks++) {
            wmma::fragment<wmma::matrix_a, 16, 16, 8, wmma::precision::tf32,
                           wmma::row_major> af[4];
            wmma::fragment<wmma::matrix_b, 16, 16, 8, wmma::precision::tf32,
                           wmma::col_major> bf[2];
#pragma unroll
            for (int mt = 0; mt < 4; mt++)
                wmma::load_matrix_sync(af[mt], &As[wm + mt * 16][ks * 8], 40);
#pragma unroll
            for (int nt = 0; nt < 2; nt++)
                wmma::load_matrix_sync(bf[nt], &Bs[wn + nt * 16][ks * 8], 40);
#pragma unroll
            for (int mt = 0; mt < 4; mt++)
#pragma unroll
                for (int nt = 0; nt < 2; nt++)
                    wmma::mma_sync(cf[mt][nt], af[mt], bf[nt], cf[mt][nt]);
        }
        __syncthreads();

        if (t + 1 < niter) {
#pragma unroll
            for (int v = 0; v < 4; v++) {
                As[lr][lk + v * 4 + 0] = wmma::__float_to_tf32(ra[v].x);
                As[lr][lk + v * 4 + 1] = wmma::__float_to_tf32(ra[v].y);
                As[lr][lk + v * 4 + 2] = wmma::__float_to_tf32(ra[v].z);
                As[lr][lk + v * 4 + 3] = wmma::__float_to_tf32(ra[v].w);
                Bs[lr][lk + v * 4 + 0] = wmma::__float_to_tf32(rb[v].x);
                Bs[lr][lk + v * 4 + 1] = wmma::__float_to_tf32(rb[v].y);
                Bs[lr][lk + v * 4 + 2] = wmma::__float_to_tf32(rb[v].z);
                Bs[lr][lk + v * 4 + 3] = wmma::__float_to_tf32(rb[v].w);
            }
            __syncthreads();
        }
    }

#pragma unroll
    for (int mt = 0; mt < 4; mt++)
#pragma unroll
        for (int nt = 0; nt < 2; nt++) {
            float* cp = Cc + (size_t)(brow + wm + mt * 16) * Nb + bcol + wn + nt * 16;
            wmma::store_matrix_sync(cp, cf[mt][nt], Nb, wmma::mem_row_major);
        }
}

// ---------------------------------------------------------------------------
// LayerNorm over contiguous 64-element groups (one warp per group)
// ---------------------------------------------------------------------------
__global__ void ln64_kernel(float* __restrict__ X, const float* __restrict__ gamma,
                            const float* __restrict__ beta, int ngroups) {
    const int warp = (blockIdx.x * blockDim.x + threadIdx.x) >> 5;
    const int lane = threadIdx.x & 31;
    if (warp >= ngroups) return;
    float* x = X + (size_t)warp * 64;
    float x0 = x[lane];
    float x1 = x[lane + 32];
    float s  = x0 + x1;
    float sq = x0 * x0 + x1 * x1;
#pragma unroll
    for (int o = 16; o > 0; o >>= 1) {
        s  += __shfl_xor_sync(0xFFFFFFFFu, s, o);
        sq += __shfl_xor_sync(0xFFFFFFFFu, sq, o);
    }
    const float mean = s * (1.f / 64.f);
    const float var  = sq * (1.f / 64.f) - mean * mean;
    const float rstd = rsqrtf(var + 1e-5f);
    x[lane]      = (x0 - mean) * rstd * gamma[lane]      + beta[lane];
    x[lane + 32] = (x1 - mean) * rstd * gamma[lane + 32] + beta[lane + 32];
}

// ---------------------------------------------------------------------------
// Fused scores + mask + scale + softmax.
// Block = (n-tile of 32 rows, one (b,h)). Full m=1024 row kept in smem.
// grid: (Nq/32, Bz*Hh), block 256, dynamic smem ~154KB.
// ---------------------------------------------------------------------------
constexpr int SS_SMEM_FLOATS = 64 * 36 + 64 * 68 + 32 * 1024;

__global__ __launch_bounds__(256)
void scores_softmax_kernel(const float* __restrict__ Q, const float* __restrict__ Kc,
                           const int* __restrict__ mask, float* __restrict__ attn) {
    extern __shared__ float sm[];
    float* Qs = sm;                       // [64 d][36] (n-padded)
    float* Ks = sm + 64 * 36;             // [64 d][68] (m-padded)
    float* S  = sm + 64 * 36 + 64 * 68;   // [32 n][1024 m]

    const int bh = blockIdx.y;
    const int b  = bh >> 4;
    const int h  = bh & 15;
    const int n0 = blockIdx.x * 32;
    const int tid = threadIdx.x;

    // load Q tile [32 n][64 d] -> Qs[d][n]
    {
        const int n  = tid >> 3;
        const int d0 = (tid & 7) * 8;
        const float* qp = Q + (size_t)(b * Nq + n0 + n) * Cd + h * 64 + d0;
        float4 q0 = *(const float4*)qp;
        float4 q1 = *(const float4*)(qp + 4);
        Qs[(d0 + 0) * 36 + n] = q0.x; Qs[(d0 + 1) * 36 + n] = q0.y;
        Qs[(d0 + 2) * 36 + n] = q0.z; Qs[(d0 + 3) * 36 + n] = q0.w;
        Qs[(d0 + 4) * 36 + n] = q1.x; Qs[(d0 + 5) * 36 + n] = q1.y;
        Qs[(d0 + 6) * 36 + n] = q1.z; Qs[(d0 + 7) * 36 + n] = q1.w;
    }

    const int ty = tid >> 5;   // 0..7  -> n = ty*4 + i
    const int tx = tid & 31;   // 0..31 -> m = tx*2 + j

    for (int mc = 0; mc < Mc; mc += 64) {
        // load K chunk [64 m][64 d] -> Ks[d][m]
        {
            const int m  = tid >> 2;
            const int d0 = (tid & 3) * 16;
            const float* kp = Kc + (size_t)(b * Mc + mc + m) * Cd + h * 64 + d0;
#pragma unroll
            for (int v = 0; v < 4; v++) {
                float4 kv = *(const float4*)(kp + v * 4);
                Ks[(d0 + v * 4 + 0) * 68 + m] = kv.x;
                Ks[(d0 + v * 4 + 1) * 68 + m] = kv.y;
                Ks[(d0 + v * 4 + 2) * 68 + m] = kv.z;
                Ks[(d0 + v * 4 + 3) * 68 + m] = kv.w;
            }
        }
        __syncthreads();

        float acc[4][2];
#pragma unroll
        for (int i = 0; i < 4; i++) { acc[i][0] = 0.f; acc[i][1] = 0.f; }

#pragma unroll 8
        for (int d = 0; d < 64; d++) {
            float4 a = *(const float4*)&Qs[d * 36 + ty * 4];   // broadcast
            float2 bb = *(const float2*)&Ks[d * 68 + tx * 2];
            float av[4] = {a.x, a.y, a.z, a.w};
#pragma unroll
            for (int i = 0; i < 4; i++) {
                acc[i][0] = fmaf(av[i], bb.x, acc[i][0]);
                acc[i][1] = fmaf(av[i], bb.y, acc[i][1]);
            }
        }

        const float scale = 0.125f;
#pragma unroll
        for (int j = 0; j < 2; j++) {
            const int m = mc + tx * 2 + j;
            const bool ok = mask[b * Mc + m] != 0;
#pragma unroll
            for (int i = 0; i < 4; i++) {
                float sv = acc[i][j] * scale;
                if (!ok) sv = -1e30f;
                S[(ty * 4 + i) * 1024 + m] = sv;
            }
        }
        __syncthreads();
    }

    // softmax: warp w handles rows w*4..w*4+3
    const int lane = tid & 31;
    const int w    = tid >> 5;
    for (int r = 0; r < 4; r++) {
        const int n = w * 4 + r;
        float* p = S + (size_t)n * 1024;

        float4 v[8];
        float mx = -1e30f;
#pragma unroll
        for (int i = 0; i < 8; i++) {
            v[i] = *(const float4*)(p + (i * 32 + lane) * 4);
            mx = fmaxf(mx, fmaxf(fmaxf(v[i].x, v[i].y), fmaxf(v[i].z, v[i].w)));
        }
#pragma unroll
        for (int o = 16; o > 0; o >>= 1) mx = fmaxf(mx, __shfl_xor_sync(0xFFFFFFFFu, mx, o));

        float sum = 0.f;
#pragma unroll
        for (int i = 0; i < 8; i++) {
            v[i].x = __expf(v[i].x - mx);
            v[i].y = __expf(v[i].y - mx);
            v[i].z = __expf(v[i].z - mx);
            v[i].w = __expf(v[i].w - mx);
            sum += v[i].x + v[i].y + v[i].z + v[i].w;
        }
#pragma unroll
        for (int o = 16; o > 0; o >>= 1) sum += __shfl_xor_sync(0xFFFFFFFFu, sum, o);
        const float inv = 1.f / sum;

        float* op = attn + ((size_t)bh * Nq + n0 + n) * Mc;
#pragma unroll
        for (int i = 0; i < 8; i++) {
            v[i].x *= inv; v[i].y *= inv; v[i].z *= inv; v[i].w *= inv;
            *(float4*)(op + (i * 32 + lane) * 4) = v[i];
        }
    }
}

// ---------------------------------------------------------------------------
// AV: O[b,n,h*64+d] = sum_m attn[bh,n,m] * V[b,m,h*64+d]
// ---------------------------------------------------------------------------
__global__ __launch_bounds__(256)
void av_kernel(const float* __restrict__ attn, const float* __restrict__ V,
               float* __restrict__ O) {
    const int bh = blockIdx.y;
    const int b  = bh >> 4;
    const int h  = bh & 15;
    const int n0 = blockIdx.x * 64;

    __shared__ float Asm[32][68];
    __shared__ float Vs[32][64];

    const int tid = threadIdx.x;
    const int ty = tid >> 4, tx = tid & 15;
    float acc[4][4];
#pragma unroll
    for (int i = 0; i < 4; i++)
#pragma unroll
        for (int j = 0; j < 4; j++) acc[i][j] = 0.f;

    for (int mc = 0; mc < Mc; mc += 32) {
        {
            const int n  = tid >> 2;
            const int ml = (tid & 3) * 8;
            const float* ap = attn + ((size_t)bh * Nq + n0 + n) * Mc + mc + ml;
            float4 a0 = *(const float4*)ap;
            float4 a1 = *(const float4*)(ap + 4);
            Asm[ml + 0][n] = a0.x; Asm[ml + 1][n] = a0.y;
            Asm[ml + 2][n] = a0.z; Asm[ml + 3][n] = a0.w;
            Asm[ml + 4][n] = a1.x; Asm[ml + 5][n] = a1.y;
            Asm[ml + 6][n] = a1.z; Asm[ml + 7][n] = a1.w;

            const int m  = tid >> 3;
            const int dl = (tid & 7) * 8;
            const float* vp = V + (size_t)(b * Mc + mc + m) * Cd + h * 64 + dl;
            *(float4*)&Vs[m][dl]     = *(const float4*)vp;
            *(float4*)&Vs[m][dl + 4] = *(const float4*)(vp + 4);
        }
        __syncthreads();
#pragma unroll
        for (int mm = 0; mm < 32; mm++) {
            float4 a = *(const float4*)&Asm[mm][ty * 4];
            float4 c = *(const float4*)&Vs[mm][tx * 4];
            float av[4] = {a.x, a.y, a.z, a.w};
            float bv[4] = {c.x, c.y, c.z, c.w};
#pragma unroll
            for (int i = 0; i < 4; i++)
#pragma unroll
                for (int j = 0; j < 4; j++)
                    acc[i][j] = fmaf(av[i], bv[j], acc[i][j]);
        }
        __syncthreads();
    }

#pragma unroll
    for (int i = 0; i < 4; i++) {
        const int n = n0 + ty * 4 + i;
        float* op = O + (size_t)(b * Nq + n) * Cd + h * 64 + tx * 4;
        *(float4*)op = make_float4(acc[i][0], acc[i][1], acc[i][2], acc[i][3]);
    }
}

// ---------------------------------------------------------------------------
// Launch
// ---------------------------------------------------------------------------
extern "C" void kernel_launch(void* const* d_in, const int* in_sizes, int n_in,
                              void* d_out, int out_size) {
    const float* query   = (const float*)d_in[0];
    const float* context = (const float*)d_in[1];
    const int*   mask    = (const int*)d_in[2];
    const float* Wq      = (const float*)d_in[3];
    const float* Wk      = (const float*)d_in[4];
    const float* Wv      = (const float*)d_in[5];
    const float* qg      = (const float*)d_in[6];
    const float* qb      = (const float*)d_in[7];
    const float* kg      = (const float*)d_in[8];
    const float* kb      = (const float*)d_in[9];
    const float* Wp      = (const float*)d_in[10];
    const float* bp      = (const float*)d_in[11];

    float* out  = (float*)d_out;                 // [B,N,C]
    float* attn = out + (size_t)Bz * Nq * Cd;    // [B,H,N,M]

    float *Qp, *Kp, *Vp, *Op;
    cudaGetSymbolAddress((void**)&Qp, g_Q);
    cudaGetSymbolAddress((void**)&Kp, g_K);
    cudaGetSymbolAddress((void**)&Vp, g_V);
    cudaGetSymbolAddress((void**)&Op, g_O);

    // Projections (tf32 tensor cores)
    {
        dim3 gq(Cd / 128, (Bz * Nq) / 128);      // 8 x 16
        gemm_tf32_128<<<gq, 256>>>(query, Wq, nullptr, Qp, Bz * Nq, Cd, Cd);
        dim3 gk(Cd / 128, (Bz * Mc) / 128);      // 8 x 64
        gemm_tf32_128<<<gk, 256>>>(context, Wk, nullptr, Kp, Bz * Mc, Cd, Cd);
        gemm_tf32_128<<<gk, 256>>>(context, Wv, nullptr, Vp, Bz * Mc, Cd, Cd);
    }

    // LayerNorm q, k
    {
        const int gq = Bz * Nq * Hh;
        const int gk = Bz * Mc * Hh;
        ln64_kernel<<<(gq * 32 + 255) / 256, 256>>>(Qp, qg, qb, gq);
        ln64_kernel<<<(gk * 32 + 255) / 256, 256>>>(Kp, kg, kb, gk);
    }

    // Fused scores + mask + softmax -> attn
    {
        const size_t smem = SS_SMEM_FLOATS * sizeof(float);
        cudaFuncSetAttribute(scores_softmax_kernel,
                             cudaFuncAttributeMaxDynamicSharedMemorySize, (int)smem);
        dim3 gs(Nq / 32, Bz * Hh);               // 8 x 128
        scores_softmax_kernel<<<gs, 256, smem>>>(Qp, Kp, mask, attn);
    }

    // attn @ V
    {
        dim3 ga(Nq / 64, Bz * Hh);               // 4 x 128
        av_kernel<<<ga, 256>>>(attn, Vp, Op);
    }

    // Output projection + bias (tf32 tensor cores)
    {
        dim3 go(Cd / 128, (Bz * Nq) / 128);      // 8 x 16
        gemm_tf32_128<<<go, 256>>>(Op, Wp, bp, out, Bz * Nq, Cd, Cd);
    }
}

// round 4
// speedup vs baseline: 1.7267x; 1.3171x over previous
#include <cuda_runtime.h>
#include <math.h>
#include <stdint.h>

// Problem constants
constexpr int Bz = 8;
constexpr int Nq = 256;
constexpr int Mc = 1024;
constexpr int Cd = 1024;
constexpr int Hh = 16;

// Scratch
__device__ float g_Q[Bz * Nq * Cd];    // 8 MB   (Q proj, fp32)
__device__ float g_K[Bz * Mc * Cd];    // 32 MB  (K proj, fp32)
__device__ float g_V[Bz * Mc * Cd];    // 32 MB  (V proj, fp32)
__device__ float g_O[Bz * Nq * Cd];    // 8 MB   (AV out, tf32-rounded)
__device__ float g_cq[Bz * Nq * Cd];   // 8 MB   (query, tf32-rounded)
__device__ float g_cc[Bz * Mc * Cd];   // 32 MB  (context, tf32-rounded)
__device__ float g_w0[Cd * Cd];        // Wq tf32
__device__ float g_w1[Cd * Cd];        // Wk tf32
__device__ float g_w2[Cd * Cd];        // Wv tf32
__device__ float g_w3[Cd * Cd];        // Wp tf32

__device__ __forceinline__ uint32_t tf32r(float x) {
    uint32_t r;
    asm("cvt.rna.tf32.f32 %0, %1;" : "=r"(r) : "f"(x));
    return r;
}

__device__ __forceinline__ void cp_async16(uint32_t saddr, const void* gptr) {
    asm volatile("cp.async.ca.shared.global [%0], [%1], 16;" ::
                 "r"(saddr), "l"(gptr));
}
__device__ __forceinline__ void cp_commit() {
    asm volatile("cp.async.commit_group;");
}
__device__ __forceinline__ void cp_wait0() {
    asm volatile("cp.async.wait_group 0;");
}

__device__ __forceinline__ void mma_tf32(float c[4], uint32_t a0, uint32_t a1,
                                         uint32_t a2, uint32_t a3,
                                         uint32_t b0, uint32_t b1) {
    asm volatile(
        "mma.sync.aligned.m16n8k8.row.col.f32.tf32.tf32.f32 "
        "{%0,%1,%2,%3}, {%4,%5,%6,%7}, {%8,%9}, {%0,%1,%2,%3};"
        : "+f"(c[0]), "+f"(c[1]), "+f"(c[2]), "+f"(c[3])
        : "r"(a0), "r"(a1), "r"(a2), "r"(a3), "r"(b0), "r"(b1));
}

// ---------------------------------------------------------------------------
// tf32 round elementwise (inputs assumed multiple of 4 elements)
// ---------------------------------------------------------------------------
__global__ void cvt_tf32_kernel(const float* __restrict__ in,
                                float* __restrict__ out, int n4) {
    int i = blockIdx.x * blockDim.x + threadIdx.x;
    if (i >= n4) return;
    float4 v = ((const float4*)in)[i];
    v.x = __uint_as_float(tf32r(v.x));
    v.y = __uint_as_float(tf32r(v.y));
    v.z = __uint_as_float(tf32r(v.z));
    v.w = __uint_as_float(tf32r(v.w));
    ((float4*)out)[i] = v;
}

// ---------------------------------------------------------------------------
// TF32 mma.sync GEMM: C[Ma,Nb] = A[Ma,K] * B[Nb,K]^T (+ bias)
// A,B already tf32-rounded. 128x128 CTA, 8 warps (2m x 4n), warp 64x32.
// kTile=32, 2-stage cp.async. smem [128][36] per matrix per stage.
// ---------------------------------------------------------------------------
constexpr int GEMM_SMEM = 2 * 2 * 128 * 36 * 4;  // 73728 bytes

__global__ __launch_bounds__(256, 2)
void gemm_tf32_mma(const float* __restrict__ A, const float* __restrict__ Bw,
                   const float* __restrict__ bias, float* __restrict__ Cc,
                   int Ma, int Nb, int K) {
    extern __shared__ float sm[];
    float* As = sm;                   // [2][128][36]
    float* Bs = sm + 2 * 128 * 36;    // [2][128][36]

    const int tid  = threadIdx.x;
    const int lane = tid & 31;
    const int w    = tid >> 5;
    const int wm   = (w & 1) * 64;
    const int wn   = (w >> 1) * 32;
    const int g    = lane >> 2;
    const int ti   = lane & 3;
    const int brow = blockIdx.y * 128;
    const int bcol = blockIdx.x * 128;

    // global load mapping: row = tid>>1, k-offset = (tid&1)*16 (+4v)
    const int lrow = tid >> 1;
    const int lk   = (tid & 1) * 16;
    const float* Ag = A  + (size_t)(brow + lrow) * K + lk;
    const float* Bg = Bw + (size_t)(bcol + lrow) * K + lk;
    const uint32_t sa = (uint32_t)__cvta_generic_to_shared(&As[lrow * 36 + lk]);
    const uint32_t sb = (uint32_t)__cvta_generic_to_shared(&Bs[lrow * 36 + lk]);
    const uint32_t stageB = 128 * 36 * 4;  // bytes per stage

    float c[4][4][4];
#pragma unroll
    for (int mt = 0; mt < 4; mt++)
#pragma unroll
        for (int nt = 0; nt < 4; nt++)
#pragma unroll
            for (int e = 0; e < 4; e++) c[mt][nt][e] = 0.f;

    const int niter = K / 32;

    // prologue: stage 0
#pragma unroll
    for (int v = 0; v < 4; v++) {
        cp_async16(sa + v * 16, Ag + v * 4);
        cp_async16(sb + v * 16, Bg + v * 4);
    }
    cp_commit();
    cp_wait0();
    __syncthreads();

    for (int t = 0; t < niter; t++) {
        if (t + 1 < niter) {
            const int k0 = (t + 1) * 32;
            const uint32_t so = ((t + 1) & 1) * stageB;
#pragma unroll
            for (int v = 0; v < 4; v++) {
                cp_async16(sa + so + v * 16, Ag + k0 + v * 4);
                cp_async16(sb + so + v * 16, Bg + k0 + v * 4);
            }
            cp_commit();
        }

        const float* as = As + (t & 1) * 128 * 36;
        const float* bs = Bs + (t & 1) * 128 * 36;

#pragma unroll
        for (int ks = 0; ks < 4; ks++) {
            const int kk = ks * 8;
            uint32_t a[4][4], b[4][2];
#pragma unroll
            for (int mt = 0; mt < 4; mt++) {
                const int r0 = wm + mt * 16 + g;
                a[mt][0] = __float_as_uint(as[r0 * 36 + kk + ti]);
                a[mt][1] = __float_as_uint(as[(r0 + 8) * 36 + kk + ti]);
                a[mt][2] = __float_as_uint(as[r0 * 36 + kk + ti + 4]);
                a[mt][3] = __float_as_uint(as[(r0 + 8) * 36 + kk + ti + 4]);
            }
#pragma unroll
            for (int nt = 0; nt < 4; nt++) {
                const int n0 = wn + nt * 8 + g;
                b[nt][0] = __float_as_uint(bs[n0 * 36 + kk + ti]);
                b[nt][1] = __float_as_uint(bs[n0 * 36 + kk + ti + 4]);
            }
#pragma unroll
            for (int mt = 0; mt < 4; mt++)
#pragma unroll
                for (int nt = 0; nt < 4; nt++)
                    mma_tf32(c[mt][nt], a[mt][0], a[mt][1], a[mt][2], a[mt][3],
                             b[nt][0], b[nt][1]);
        }

        if (t + 1 < niter) {
            cp_wait0();
            __syncthreads();
        }
    }

    // epilogue: c0:(g,2t) c1:(g,2t+1) c2:(g+8,2t) c3:(g+8,2t+1)
#pragma unroll
    for (int mt = 0; mt < 4; mt++) {
#pragma unroll
        for (int nt = 0; nt < 4; nt++) {
            const int row0 = brow + wm + mt * 16 + g;
            const int col0 = bcol + wn + nt * 8 + 2 * ti;
            float b0 = 0.f, b1 = 0.f;
            if (bias != nullptr) { b0 = bias[col0]; b1 = bias[col0 + 1]; }
            *(float2*)(Cc + (size_t)row0 * Nb + col0) =
                make_float2(c[mt][nt][0] + b0, c[mt][nt][1] + b1);
            *(float2*)(Cc + (size_t)(row0 + 8) * Nb + col0) =
                make_float2(c[mt][nt][2] + b0, c[mt][nt][3] + b1);
        }
    }
}

// ---------------------------------------------------------------------------
// LayerNorm over contiguous 64-element groups (one warp per group)
// ---------------------------------------------------------------------------
__global__ void ln64_kernel(float* __restrict__ X, const float* __restrict__ gamma,
                            const float* __restrict__ beta, int ngroups) {
    const int warp = (blockIdx.x * blockDim.x + threadIdx.x) >> 5;
    const int lane = threadIdx.x & 31;
    if (warp >= ngroups) return;
    float* x = X + (size_t)warp * 64;
    float x0 = x[lane];
    float x1 = x[lane + 32];
    float s  = x0 + x1;
    float sq = x0 * x0 + x1 * x1;
#pragma unroll
    for (int o = 16; o > 0; o >>= 1) {
        s  += __shfl_xor_sync(0xFFFFFFFFu, s, o);
        sq += __shfl_xor_sync(0xFFFFFFFFu, sq, o);
    }
    const float mean = s * (1.f / 64.f);
    const float var  = sq * (1.f / 64.f) - mean * mean;
    const float rstd = rsqrtf(var + 1e-5f);
    x[lane]      = (x0 - mean) * rstd * gamma[lane]      + beta[lane];
    x[lane + 32] = (x1 - mean) * rstd * gamma[lane + 32] + beta[lane + 32];
}

// ---------------------------------------------------------------------------
// Fused scores + mask + scale + softmax. Block = 32 q-rows x one (b,h).
// ---------------------------------------------------------------------------
constexpr int SS_SMEM_FLOATS = 64 * 36 + 64 * 68 + 32 * 1024;

__global__ __launch_bounds__(256)
void scores_softmax_kernel(const float* __restrict__ Q, const float* __restrict__ Kc,
                           const int* __restrict__ mask, float* __restrict__ attn) {
    extern __shared__ float sm[];
    float* Qs = sm;                       // [64 d][36]
    float* Ks = sm + 64 * 36;             // [64 d][68]
    float* S  = sm + 64 * 36 + 64 * 68;   // [32 n][1024 m]

    const int bh = blockIdx.y;
    const int b  = bh >> 4;
    const int h  = bh & 15;
    const int n0 = blockIdx.x * 32;
    const int tid = threadIdx.x;

    {
        const int n  = tid >> 3;
        const int d0 = (tid & 7) * 8;
        const float* qp = Q + (size_t)(b * Nq + n0 + n) * Cd + h * 64 + d0;
        float4 q0 = *(const float4*)qp;
        float4 q1 = *(const float4*)(qp + 4);
        Qs[(d0 + 0) * 36 + n] = q0.x; Qs[(d0 + 1) * 36 + n] = q0.y;
        Qs[(d0 + 2) * 36 + n] = q0.z; Qs[(d0 + 3) * 36 + n] = q0.w;
        Qs[(d0 + 4) * 36 + n] = q1.x; Qs[(d0 + 5) * 36 + n] = q1.y;
        Qs[(d0 + 6) * 36 + n] = q1.z; Qs[(d0 + 7) * 36 + n] = q1.w;
    }

    const int ty = tid >> 5;
    const int tx = tid & 31;

    for (int mc = 0; mc < Mc; mc += 64) {
        {
            const int m  = tid >> 2;
            const int d0 = (tid & 3) * 16;
            const float* kp = Kc + (size_t)(b * Mc + mc + m) * Cd + h * 64 + d0;
#pragma unroll
            for (int v = 0; v < 4; v++) {
                float4 kv = *(const float4*)(kp + v * 4);
                Ks[(d0 + v * 4 + 0) * 68 + m] = kv.x;
                Ks[(d0 + v * 4 + 1) * 68 + m] = kv.y;
                Ks[(d0 + v * 4 + 2) * 68 + m] = kv.z;
                Ks[(d0 + v * 4 + 3) * 68 + m] = kv.w;
            }
        }
        __syncthreads();

        float acc[4][2];
#pragma unroll
        for (int i = 0; i < 4; i++) { acc[i][0] = 0.f; acc[i][1] = 0.f; }

#pragma unroll 8
        for (int d = 0; d < 64; d++) {
            float4 a = *(const float4*)&Qs[d * 36 + ty * 4];
            float2 bb = *(const float2*)&Ks[d * 68 + tx * 2];
            float av[4] = {a.x, a.y, a.z, a.w};
#pragma unroll
            for (int i = 0; i < 4; i++) {
                acc[i][0] = fmaf(av[i], bb.x, acc[i][0]);
                acc[i][1] = fmaf(av[i], bb.y, acc[i][1]);
            }
        }

        const float scale = 0.125f;
#pragma unroll
        for (int j = 0; j < 2; j++) {
            const int m = mc + tx * 2 + j;
            const bool ok = mask[b * Mc + m] != 0;
#pragma unroll
            for (int i = 0; i < 4; i++) {
                float sv = acc[i][j] * scale;
                if (!ok) sv = -1e30f;
                S[(ty * 4 + i) * 1024 + m] = sv;
            }
        }
        __syncthreads();
    }

    const int lane = tid & 31;
    const int wz   = tid >> 5;
    for (int r = 0; r < 4; r++) {
        const int n = wz * 4 + r;
        float* p = S + (size_t)n * 1024;

        float4 v[8];
        float mx = -1e30f;
#pragma unroll
        for (int i = 0; i < 8; i++) {
            v[i] = *(const float4*)(p + (i * 32 + lane) * 4);
            mx = fmaxf(mx, fmaxf(fmaxf(v[i].x, v[i].y), fmaxf(v[i].z, v[i].w)));
        }
#pragma unroll
        for (int o = 16; o > 0; o >>= 1) mx = fmaxf(mx, __shfl_xor_sync(0xFFFFFFFFu, mx, o));

        float sum = 0.f;
#pragma unroll
        for (int i = 0; i < 8; i++) {
            v[i].x = __expf(v[i].x - mx);
            v[i].y = __expf(v[i].y - mx);
            v[i].z = __expf(v[i].z - mx);
            v[i].w = __expf(v[i].w - mx);
            sum += v[i].x + v[i].y + v[i].z + v[i].w;
        }
#pragma unroll
        for (int o = 16; o > 0; o >>= 1) sum += __shfl_xor_sync(0xFFFFFFFFu, sum, o);
        const float inv = 1.f / sum;

        float* op = attn + ((size_t)bh * Nq + n0 + n) * Mc;
#pragma unroll
        for (int i = 0; i < 8; i++) {
            v[i].x *= inv; v[i].y *= inv; v[i].z *= inv; v[i].w *= inv;
            *(float4*)(op + (i * 32 + lane) * 4) = v[i];
        }
    }
}

// ---------------------------------------------------------------------------
// AV: O[b,n,h*64+d] = sum_m attn[bh,n,m] * V[b,m,h*64+d]; out tf32-rounded
// ---------------------------------------------------------------------------
__global__ __launch_bounds__(256)
void av_kernel(const float* __restrict__ attn, const float* __restrict__ V,
               float* __restrict__ O) {
    const int bh = blockIdx.y;
    const int b  = bh >> 4;
    const int h  = bh & 15;
    const int n0 = blockIdx.x * 64;

    __shared__ float Asm[32][68];
    __shared__ float Vs[32][64];

    const int tid = threadIdx.x;
    const int ty = tid >> 4, tx = tid & 15;
    float acc[4][4];
#pragma unroll
    for (int i = 0; i < 4; i++)
#pragma unroll
        for (int j = 0; j < 4; j++) acc[i][j] = 0.f;

    for (int mc = 0; mc < Mc; mc += 32) {
        {
            const int n  = tid >> 2;
            const int ml = (tid & 3) * 8;
            const float* ap = attn + ((size_t)bh * Nq + n0 + n) * Mc + mc + ml;
            float4 a0 = *(const float4*)ap;
            float4 a1 = *(const float4*)(ap + 4);
            Asm[ml + 0][n] = a0.x; Asm[ml + 1][n] = a0.y;
            Asm[ml + 2][n] = a0.z; Asm[ml + 3][n] = a0.w;
            Asm[ml + 4][n] = a1.x; Asm[ml + 5][n] = a1.y;
            Asm[ml + 6][n] = a1.z; Asm[ml + 7][n] = a1.w;

            const int m  = tid >> 3;
            const int dl = (tid & 7) * 8;
            const float* vp = V + (size_t)(b * Mc + mc + m) * Cd + h * 64 + dl;
            *(float4*)&Vs[m][dl]     = *(const float4*)vp;
            *(float4*)&Vs[m][dl + 4] = *(const float4*)(vp + 4);
        }
        __syncthreads();
#pragma unroll
        for (int mm = 0; mm < 32; mm++) {
            float4 a = *(const float4*)&Asm[mm][ty * 4];
            float4 cv = *(const float4*)&Vs[mm][tx * 4];
            float av[4] = {a.x, a.y, a.z, a.w};
            float bv[4] = {cv.x, cv.y, cv.z, cv.w};
#pragma unroll
            for (int i = 0; i < 4; i++)
#pragma unroll
                for (int j = 0; j < 4; j++)
                    acc[i][j] = fmaf(av[i], bv[j], acc[i][j]);
        }
        __syncthreads();
    }

#pragma unroll
    for (int i = 0; i < 4; i++) {
        const int n = n0 + ty * 4 + i;
        float* op = O + (size_t)(b * Nq + n) * Cd + h * 64 + tx * 4;
        *(float4*)op = make_float4(__uint_as_float(tf32r(acc[i][0])),
                                   __uint_as_float(tf32r(acc[i][1])),
                                   __uint_as_float(tf32r(acc[i][2])),
                                   __uint_as_float(tf32r(acc[i][3])));
    }
}

// ---------------------------------------------------------------------------
// Launch
// ---------------------------------------------------------------------------
extern "C" void kernel_launch(void* const* d_in, const int* in_sizes, int n_in,
                              void* d_out, int out_size) {
    const float* query   = (const float*)d_in[0];
    const float* context = (const float*)d_in[1];
    const int*   mask    = (const int*)d_in[2];
    const float* Wq      = (const float*)d_in[3];
    const float* Wk      = (const float*)d_in[4];
    const float* Wv      = (const float*)d_in[5];
    const float* qg      = (const float*)d_in[6];
    const float* qb      = (const float*)d_in[7];
    const float* kg      = (const float*)d_in[8];
    const float* kb      = (const float*)d_in[9];
    const float* Wp      = (const float*)d_in[10];
    const float* bp      = (const float*)d_in[11];

    float* out  = (float*)d_out;                 // [B,N,C]
    float* attn = out + (size_t)Bz * Nq * Cd;    // [B,H,N,M]

    float *Qp, *Kp, *Vp, *Op, *cq, *cc, *w0, *w1, *w2, *w3;
    cudaGetSymbolAddress((void**)&Qp, g_Q);
    cudaGetSymbolAddress((void**)&Kp, g_K);
    cudaGetSymbolAddress((void**)&Vp, g_V);
    cudaGetSymbolAddress((void**)&Op, g_O);
    cudaGetSymbolAddress((void**)&cq, g_cq);
    cudaGetSymbolAddress((void**)&cc, g_cc);
    cudaGetSymbolAddress((void**)&w0, g_w0);
    cudaGetSymbolAddress((void**)&w1, g_w1);
    cudaGetSymbolAddress((void**)&w2, g_w2);
    cudaGetSymbolAddress((void**)&w3, g_w3);

    cudaFuncSetAttribute(gemm_tf32_mma,
                         cudaFuncAttributeMaxDynamicSharedMemorySize, GEMM_SMEM);
    cudaFuncSetAttribute(scores_softmax_kernel,
                         cudaFuncAttributeMaxDynamicSharedMemorySize,
                         (int)(SS_SMEM_FLOATS * sizeof(float)));

    // tf32 pre-conversion
    {
        const int nQ = Bz * Nq * Cd / 4, nC = Bz * Mc * Cd / 4, nW = Cd * Cd / 4;
        cvt_tf32_kernel<<<(nQ + 255) / 256, 256>>>(query, cq, nQ);
        cvt_tf32_kernel<<<(nC + 255) / 256, 256>>>(context, cc, nC);
        cvt_tf32_kernel<<<(nW + 255) / 256, 256>>>(Wq, w0, nW);
        cvt_tf32_kernel<<<(nW + 255) / 256, 256>>>(Wk, w1, nW);
        cvt_tf32_kernel<<<(nW + 255) / 256, 256>>>(Wv, w2, nW);
        cvt_tf32_kernel<<<(nW + 255) / 256, 256>>>(Wp, w3, nW);
    }

    // Projections
    {
        dim3 gq(Cd / 128, (Bz * Nq) / 128);      // 8 x 16
        gemm_tf32_mma<<<gq, 256, GEMM_SMEM>>>(cq, w0, nullptr, Qp, Bz * Nq, Cd, Cd);
        dim3 gk(Cd / 128, (Bz * Mc) / 128);      // 8 x 64
        gemm_tf32_mma<<<gk, 256, GEMM_SMEM>>>(cc, w1, nullptr, Kp, Bz * Mc, Cd, Cd);
        gemm_tf32_mma<<<gk, 256, GEMM_SMEM>>>(cc, w2, nullptr, Vp, Bz * Mc, Cd, Cd);
    }

    // LayerNorm q, k
    {
        const int gq = Bz * Nq * Hh;
        const int gk = Bz * Mc * Hh;
        ln64_kernel<<<(gq * 32 + 255) / 256, 256>>>(Qp, qg, qb, gq);
        ln64_kernel<<<(gk * 32 + 255) / 256, 256>>>(Kp, kg, kb, gk);
    }

    // Fused scores + mask + softmax -> attn
    {
        dim3 gs(Nq / 32, Bz * Hh);
        scores_softmax_kernel<<<gs, 256, SS_SMEM_FLOATS * sizeof(float)>>>(
            Qp, Kp, mask, attn);
    }

    // attn @ V  (writes tf32-rounded O)
    {
        dim3 ga(Nq / 64, Bz * Hh);
        av_kernel<<<ga, 256>>>(attn, Vp, Op);
    }

    // Output projection + bias
    {
        dim3 go(Cd / 128, (Bz * Nq) / 128);
        gemm_tf32_mma<<<go, 256, GEMM_SMEM>>>(Op, w3, bp, out, Bz * Nq, Cd, Cd);
    }
}

// round 6
// speedup vs baseline: 2.2705x; 1.3150x over previous
#include <cuda_runtime.h>
#include <cuda_fp16.h>
#include <math.h>
#include <stdint.h>

// Problem constants
constexpr int Bz = 8;
constexpr int Nq = 256;
constexpr int Mc = 1024;
constexpr int Cd = 1024;
constexpr int Hh = 16;

// Scratch
__device__ float  g_Q[Bz * Nq * Cd];    // Q proj (fp32)
__device__ float  g_K[Bz * Mc * Cd];    // K proj (fp32)
__device__ float  g_V[Bz * Mc * Cd];    // V proj (fp32)
__device__ __half g_hO[Bz * Nq * Cd];   // AV out (fp16)
__device__ __half g_hq[Bz * Nq * Cd];   // query fp16
__device__ __half g_hc[Bz * Mc * Cd];   // context fp16
__device__ __half g_w0[Cd * Cd];        // Wq fp16
__device__ __half g_w1[Cd * Cd];        // Wk fp16
__device__ __half g_w2[Cd * Cd];        // Wv fp16
__device__ __half g_w3[Cd * Cd];        // Wp fp16

// ---------------------------------------------------------------------------
// PTX helpers (legacy path only — this build rejects tcgen05 / sm_103a feats)
// ---------------------------------------------------------------------------
__device__ __forceinline__ void cp_async16(uint32_t saddr, const void* gptr) {
    asm volatile("cp.async.ca.shared.global [%0], [%1], 16;" ::
                 "r"(saddr), "l"(gptr));
}
__device__ __forceinline__ void cp_commit() { asm volatile("cp.async.commit_group;"); }
__device__ __forceinline__ void cp_wait0()  { asm volatile("cp.async.wait_group 0;"); }

__device__ __forceinline__ void mma_f16_16816(float c[4], uint32_t a0, uint32_t a1,
                                              uint32_t a2, uint32_t a3,
                                              uint32_t b0, uint32_t b1) {
    asm volatile(
        "mma.sync.aligned.m16n8k16.row.col.f32.f16.f16.f32 "
        "{%0,%1,%2,%3}, {%4,%5,%6,%7}, {%8,%9}, {%0,%1,%2,%3};"
        : "+f"(c[0]), "+f"(c[1]), "+f"(c[2]), "+f"(c[3])
        : "r"(a0), "r"(a1), "r"(a2), "r"(a3), "r"(b0), "r"(b1));
}

// ---------------------------------------------------------------------------
// fp32 -> fp16 conversion (n4 = element count / 4)
// ---------------------------------------------------------------------------
__global__ void cvt_f16_kernel(const float* __restrict__ in,
                               __half* __restrict__ out, int n4) {
    int i = blockIdx.x * blockDim.x + threadIdx.x;
    if (i >= n4) return;
    float4 v = ((const float4*)in)[i];
    ((__half2*)out)[2 * i]     = __floats2half2_rn(v.x, v.y);
    ((__half2*)out)[2 * i + 1] = __floats2half2_rn(v.z, v.w);
}

// ---------------------------------------------------------------------------
// FP16 mma.sync GEMM: C[Ma,Nb] = A[Ma,K] * B[Nb,K]^T (+ bias), fp32 out.
// A,B fp16. 128x128 CTA, 8 warps (2m x 4n), warp 64x32.
// kTile=64 halves, 2-stage cp.async. smem [128][72] halves per matrix/stage.
// ---------------------------------------------------------------------------
constexpr int GEMM_SMEM = 2 * 2 * 128 * 72 * 2;  // 73728 bytes

__global__ __launch_bounds__(256, 2)
void gemm_f16_mma(const __half* __restrict__ A, const __half* __restrict__ Bw,
                  const float* __restrict__ bias, float* __restrict__ Cc,
                  int Nb, int K) {
    extern __shared__ __half smh[];
    __half* As = smh;                   // [2][128][72]
    __half* Bs = smh + 2 * 128 * 72;    // [2][128][72]

    const int tid  = threadIdx.x;
    const int lane = tid & 31;
    const int w    = tid >> 5;
    const int wm   = (w & 1) * 64;
    const int wn   = (w >> 1) * 32;
    const int g    = lane >> 2;
    const int ti   = lane & 3;
    const int brow = blockIdx.y * 128;
    const int bcol = blockIdx.x * 128;

    // global->smem: row = tid>>1, 32-half slab = (tid&1)*32, 4x16B per thread
    const int lrow = tid >> 1;
    const int lh   = (tid & 1) * 32;       // half offset within row
    const __half* Ag = A  + (size_t)(brow + lrow) * K + lh;
    const __half* Bg = Bw + (size_t)(bcol + lrow) * K + lh;
    const uint32_t sa = (uint32_t)__cvta_generic_to_shared(&As[lrow * 72 + lh]);
    const uint32_t sb = (uint32_t)__cvta_generic_to_shared(&Bs[lrow * 72 + lh]);
    const uint32_t stageB = 128 * 72 * 2;  // bytes per stage

    float c[4][4][4];
#pragma unroll
    for (int mt = 0; mt < 4; mt++)
#pragma unroll
        for (int nt = 0; nt < 4; nt++)
#pragma unroll
            for (int e = 0; e < 4; e++) c[mt][nt][e] = 0.f;

    const int niter = K / 64;

    // prologue: stage 0
#pragma unroll
    for (int v = 0; v < 4; v++) {
        cp_async16(sa + v * 16, Ag + v * 8);
        cp_async16(sb + v * 16, Bg + v * 8);
    }
    cp_commit();
    cp_wait0();
    __syncthreads();

    for (int t = 0; t < niter; t++) {
        if (t + 1 < niter) {
            const int k0 = (t + 1) * 64;
            const uint32_t so = ((t + 1) & 1) * stageB;
#pragma unroll
            for (int v = 0; v < 4; v++) {
                cp_async16(sa + so + v * 16, Ag + k0 + v * 8);
                cp_async16(sb + so + v * 16, Bg + k0 + v * 8);
            }
            cp_commit();
        }

        const __half* as = As + (t & 1) * 128 * 72;
        const __half* bs = Bs + (t & 1) * 128 * 72;

#pragma unroll
        for (int ks = 0; ks < 4; ks++) {
            const int kk = ks * 16;
            uint32_t a[4][4], b[4][2];
#pragma unroll
            for (int mt = 0; mt < 4; mt++) {
                const int r0 = wm + mt * 16 + g;
                a[mt][0] = *(const uint32_t*)&as[r0 * 72 + kk + 2 * ti];
                a[mt][1] = *(const uint32_t*)&as[(r0 + 8) * 72 + kk + 2 * ti];
                a[mt][2] = *(const uint32_t*)&as[r0 * 72 + kk + 2 * ti + 8];
                a[mt][3] = *(const uint32_t*)&as[(r0 + 8) * 72 + kk + 2 * ti + 8];
            }
#pragma unroll
            for (int nt = 0; nt < 4; nt++) {
                const int n0 = wn + nt * 8 + g;
                b[nt][0] = *(const uint32_t*)&bs[n0 * 72 + kk + 2 * ti];
                b[nt][1] = *(const uint32_t*)&bs[n0 * 72 + kk + 2 * ti + 8];
            }
#pragma unroll
            for (int mt = 0; mt < 4; mt++)
#pragma unroll
                for (int nt = 0; nt < 4; nt++)
                    mma_f16_16816(c[mt][nt], a[mt][0], a[mt][1], a[mt][2],
                                  a[mt][3], b[nt][0], b[nt][1]);
        }

        if (t + 1 < niter) {
            cp_wait0();
            __syncthreads();
        }
    }

    // epilogue: c0:(g,2t) c1:(g,2t+1) c2:(g+8,2t) c3:(g+8,2t+1)
#pragma unroll
    for (int mt = 0; mt < 4; mt++) {
#pragma unroll
        for (int nt = 0; nt < 4; nt++) {
            const int row0 = brow + wm + mt * 16 + g;
            const int col0 = bcol + wn + nt * 8 + 2 * ti;
            float b0 = 0.f, b1 = 0.f;
            if (bias != nullptr) { b0 = bias[col0]; b1 = bias[col0 + 1]; }
            *(float2*)(Cc + (size_t)row0 * Nb + col0) =
                make_float2(c[mt][nt][0] + b0, c[mt][nt][1] + b1);
            *(float2*)(Cc + (size_t)(row0 + 8) * Nb + col0) =
                make_float2(c[mt][nt][2] + b0, c[mt][nt][3] + b1);
        }
    }
}

// ---------------------------------------------------------------------------
// LayerNorm over contiguous 64-element groups (one warp per group)
// ---------------------------------------------------------------------------
__global__ void ln64_kernel(float* __restrict__ X, const float* __restrict__ gamma,
                            const float* __restrict__ beta, int ngroups) {
    const int warp = (blockIdx.x * blockDim.x + threadIdx.x) >> 5;
    const int lane = threadIdx.x & 31;
    if (warp >= ngroups) return;
    float* x = X + (size_t)warp * 64;
    float x0 = x[lane];
    float x1 = x[lane + 32];
    float s  = x0 + x1;
    float sq = x0 * x0 + x1 * x1;
#pragma unroll
    for (int o = 16; o > 0; o >>= 1) {
        s  += __shfl_xor_sync(0xFFFFFFFFu, s, o);
        sq += __shfl_xor_sync(0xFFFFFFFFu, sq, o);
    }
    const float mean = s * (1.f / 64.f);
    const float var  = sq * (1.f / 64.f) - mean * mean;
    const float rstd = rsqrtf(var + 1e-5f);
    x[lane]      = (x0 - mean) * rstd * gamma[lane]      + beta[lane];
    x[lane + 32] = (x1 - mean) * rstd * gamma[lane + 32] + beta[lane + 32];
}

// ---------------------------------------------------------------------------
// Fused scores + mask + scale + softmax. Block = 32 q-rows x one (b,h).
// ---------------------------------------------------------------------------
constexpr int SS_SMEM_FLOATS = 64 * 36 + 64 * 68 + 32 * 1024;

__global__ __launch_bounds__(256)
void scores_softmax_kernel(const float* __restrict__ Q, const float* __restrict__ Kc,
                           const int* __restrict__ mask, float* __restrict__ attn) {
    extern __shared__ float sm[];
    float* Qs = sm;                       // [64 d][36]
    float* Ks = sm + 64 * 36;             // [64 d][68]
    float* S  = sm + 64 * 36 + 64 * 68;   // [32 n][1024 m]

    const int bh = blockIdx.y;
    const int b  = bh >> 4;
    const int h  = bh & 15;
    const int n0 = blockIdx.x * 32;
    const int tid = threadIdx.x;

    {
        const int n  = tid >> 3;
        const int d0 = (tid & 7) * 8;
        const float* qp = Q + (size_t)(b * Nq + n0 + n) * Cd + h * 64 + d0;
        float4 q0 = *(const float4*)qp;
        float4 q1 = *(const float4*)(qp + 4);
        Qs[(d0 + 0) * 36 + n] = q0.x; Qs[(d0 + 1) * 36 + n] = q0.y;
        Qs[(d0 + 2) * 36 + n] = q0.z; Qs[(d0 + 3) * 36 + n] = q0.w;
        Qs[(d0 + 4) * 36 + n] = q1.x; Qs[(d0 + 5) * 36 + n] = q1.y;
        Qs[(d0 + 6) * 36 + n] = q1.z; Qs[(d0 + 7) * 36 + n] = q1.w;
    }

    const int ty = tid >> 5;
    const int tx = tid & 31;

    for (int mc = 0; mc < Mc; mc += 64) {
        {
            const int m  = tid >> 2;
            const int d0 = (tid & 3) * 16;
            const float* kp = Kc + (size_t)(b * Mc + mc + m) * Cd + h * 64 + d0;
#pragma unroll
            for (int v = 0; v < 4; v++) {
                float4 kv = *(const float4*)(kp + v * 4);
                Ks[(d0 + v * 4 + 0) * 68 + m] = kv.x;
                Ks[(d0 + v * 4 + 1) * 68 + m] = kv.y;
                Ks[(d0 + v * 4 + 2) * 68 + m] = kv.z;
                Ks[(d0 + v * 4 + 3) * 68 + m] = kv.w;
            }
        }
        __syncthreads();

        float acc[4][2];
#pragma unroll
        for (int i = 0; i < 4; i++) { acc[i][0] = 0.f; acc[i][1] = 0.f; }

#pragma unroll 8
        for (int d = 0; d < 64; d++) {
            float4 a = *(const float4*)&Qs[d * 36 + ty * 4];
            float2 bb = *(const float2*)&Ks[d * 68 + tx * 2];
            float av[4] = {a.x, a.y, a.z, a.w};
#pragma unroll
            for (int i = 0; i < 4; i++) {
                acc[i][0] = fmaf(av[i], bb.x, acc[i][0]);
                acc[i][1] = fmaf(av[i], bb.y, acc[i][1]);
            }
        }

        const float scale = 0.125f;
#pragma unroll
        for (int j = 0; j < 2; j++) {
            const int m = mc + tx * 2 + j;
            const bool ok = mask[b * Mc + m] != 0;
#pragma unroll
            for (int i = 0; i < 4; i++) {
                float sv = acc[i][j] * scale;
                if (!ok) sv = -1e30f;
                S[(ty * 4 + i) * 1024 + m] = sv;
            }
        }
        __syncthreads();
    }

    const int lane = tid & 31;
    const int wz   = tid >> 5;
    for (int r = 0; r < 4; r++) {
        const int n = wz * 4 + r;
        float* p = S + (size_t)n * 1024;

        float4 v[8];
        float mx = -1e30f;
#pragma unroll
        for (int i = 0; i < 8; i++) {
            v[i] = *(const float4*)(p + (i * 32 + lane) * 4);
            mx = fmaxf(mx, fmaxf(fmaxf(v[i].x, v[i].y), fmaxf(v[i].z, v[i].w)));
        }
#pragma unroll
        for (int o = 16; o > 0; o >>= 1) mx = fmaxf(mx, __shfl_xor_sync(0xFFFFFFFFu, mx, o));

        float sum = 0.f;
#pragma unroll
        for (int i = 0; i < 8; i++) {
            v[i].x = __expf(v[i].x - mx);
            v[i].y = __expf(v[i].y - mx);
            v[i].z = __expf(v[i].z - mx);
            v[i].w = __expf(v[i].w - mx);
            sum += v[i].x + v[i].y + v[i].z + v[i].w;
        }
#pragma unroll
        for (int o = 16; o > 0; o >>= 1) sum += __shfl_xor_sync(0xFFFFFFFFu, sum, o);
        const float inv = 1.f / sum;

        float* op = attn + ((size_t)bh * Nq + n0 + n) * Mc;
#pragma unroll
        for (int i = 0; i < 8; i++) {
            v[i].x *= inv; v[i].y *= inv; v[i].z *= inv; v[i].w *= inv;
            *(float4*)(op + (i * 32 + lane) * 4) = v[i];
        }
    }
}

// ---------------------------------------------------------------------------
// AV: O[b,n,h*64+d] = sum_m attn[bh,n,m] * V[b,m,h*64+d]; fp16 output
// ---------------------------------------------------------------------------
__global__ __launch_bounds__(256)
void av_kernel(const float* __restrict__ attn, const float* __restrict__ V,
               __half* __restrict__ O) {
    const int bh = blockIdx.y;
    const int b  = bh >> 4;
    const int h  = bh & 15;
    const int n0 = blockIdx.x * 64;

    __shared__ float Asm[32][68];
    __shared__ float Vs[32][64];

    const int tid = threadIdx.x;
    const int ty = tid >> 4, tx = tid & 15;
    float acc[4][4];
#pragma unroll
    for (int i = 0; i < 4; i++)
#pragma unroll
        for (int j = 0; j < 4; j++) acc[i][j] = 0.f;

    for (int mc = 0; mc < Mc; mc += 32) {
        {
            const int n  = tid >> 2;
            const int ml = (tid & 3) * 8;
            const float* ap = attn + ((size_t)bh * Nq + n0 + n) * Mc + mc + ml;
            float4 a0 = *(const float4*)ap;
            float4 a1 = *(const float4*)(ap + 4);
            Asm[ml + 0][n] = a0.x; Asm[ml + 1][n] = a0.y;
            Asm[ml + 2][n] = a0.z; Asm[ml + 3][n] = a0.w;
            Asm[ml + 4][n] = a1.x; Asm[ml + 5][n] = a1.y;
            Asm[ml + 6][n] = a1.z; Asm[ml + 7][n] = a1.w;

            const int m  = tid >> 3;
            const int dl = (tid & 7) * 8;
            const float* vp = V + (size_t)(b * Mc + mc + m) * Cd + h * 64 + dl;
            *(float4*)&Vs[m][dl]     = *(const float4*)vp;
            *(float4*)&Vs[m][dl + 4] = *(const float4*)(vp + 4);
        }
        __syncthreads();
#pragma unroll
        for (int mm = 0; mm < 32; mm++) {
            float4 a = *(const float4*)&Asm[mm][ty * 4];
            float4 cv = *(const float4*)&Vs[mm][tx * 4];
            float av[4] = {a.x, a.y, a.z, a.w};
            float bv[4] = {cv.x, cv.y, cv.z, cv.w};
#pragma unroll
            for (int i = 0; i < 4; i++)
#pragma unroll
                for (int j = 0; j < 4; j++)
                    acc[i][j] = fmaf(av[i], bv[j], acc[i][j]);
        }
        __syncthreads();
    }

#pragma unroll
    for (int i = 0; i < 4; i++) {
        const int n = n0 + ty * 4 + i;
        __half* op = O + (size_t)(b * Nq + n) * Cd + h * 64 + tx * 4;
        *(__half2*)op       = __floats2half2_rn(acc[i][0], acc[i][1]);
        *(__half2*)(op + 2) = __floats2half2_rn(acc[i][2], acc[i][3]);
    }
}

// ---------------------------------------------------------------------------
// Launch
// ---------------------------------------------------------------------------
extern "C" void kernel_launch(void* const* d_in, const int* in_sizes, int n_in,
                              void* d_out, int out_size) {
    const float* query   = (const float*)d_in[0];
    const float* context = (const float*)d_in[1];
    const int*   mask    = (const int*)d_in[2];
    const float* Wq      = (const float*)d_in[3];
    const float* Wk      = (const float*)d_in[4];
    const float* Wv      = (const float*)d_in[5];
    const float* qg      = (const float*)d_in[6];
    const float* qb      = (const float*)d_in[7];
    const float* kg      = (const float*)d_in[8];
    const float* kb      = (const float*)d_in[9];
    const float* Wp      = (const float*)d_in[10];
    const float* bp      = (const float*)d_in[11];

    float* out  = (float*)d_out;                 // [B,N,C]
    float* attn = out + (size_t)Bz * Nq * Cd;    // [B,H,N,M]

    float *Qp, *Kp, *Vp;
    __half *hO, *hq, *hc, *w0, *w1, *w2, *w3;
    cudaGetSymbolAddress((void**)&Qp, g_Q);
    cudaGetSymbolAddress((void**)&Kp, g_K);
    cudaGetSymbolAddress((void**)&Vp, g_V);
    cudaGetSymbolAddress((void**)&hO, g_hO);
    cudaGetSymbolAddress((void**)&hq, g_hq);
    cudaGetSymbolAddress((void**)&hc, g_hc);
    cudaGetSymbolAddress((void**)&w0, g_w0);
    cudaGetSymbolAddress((void**)&w1, g_w1);
    cudaGetSymbolAddress((void**)&w2, g_w2);
    cudaGetSymbolAddress((void**)&w3, g_w3);

    cudaFuncSetAttribute(gemm_f16_mma,
                         cudaFuncAttributeMaxDynamicSharedMemorySize, GEMM_SMEM);
    cudaFuncSetAttribute(scores_softmax_kernel,
                         cudaFuncAttributeMaxDynamicSharedMemorySize,
                         (int)(SS_SMEM_FLOATS * sizeof(float)));

    // fp16 pre-conversion
    {
        const int nQ = Bz * Nq * Cd / 4, nC = Bz * Mc * Cd / 4, nW = Cd * Cd / 4;
        cvt_f16_kernel<<<(nQ + 255) / 256, 256>>>(query, hq, nQ);
        cvt_f16_kernel<<<(nC + 255) / 256, 256>>>(context, hc, nC);
        cvt_f16_kernel<<<(nW + 255) / 256, 256>>>(Wq, w0, nW);
        cvt_f16_kernel<<<(nW + 255) / 256, 256>>>(Wk, w1, nW);
        cvt_f16_kernel<<<(nW + 255) / 256, 256>>>(Wv, w2, nW);
        cvt_f16_kernel<<<(nW + 255) / 256, 256>>>(Wp, w3, nW);
    }

    // Projections (fp16 mma.sync)
    {
        dim3 gq(Cd / 128, (Bz * Nq) / 128);      // 8 x 16
        gemm_f16_mma<<<gq, 256, GEMM_SMEM>>>(hq, w0, nullptr, Qp, Cd, Cd);
        dim3 gk(Cd / 128, (Bz * Mc) / 128);      // 8 x 64
        gemm_f16_mma<<<gk, 256, GEMM_SMEM>>>(hc, w1, nullptr, Kp, Cd, Cd);
        gemm_f16_mma<<<gk, 256, GEMM_SMEM>>>(hc, w2, nullptr, Vp, Cd, Cd);
    }

    // LayerNorm q, k
    {
        const int gq = Bz * Nq * Hh;
        const int gk = Bz * Mc * Hh;
        ln64_kernel<<<(gq * 32 + 255) / 256, 256>>>(Qp, qg, qb, gq);
        ln64_kernel<<<(gk * 32 + 255) / 256, 256>>>(Kp, kg, kb, gk);
    }

    // Fused scores + mask + softmax -> attn
    {
        dim3 gs(Nq / 32, Bz * Hh);
        scores_softmax_kernel<<<gs, 256, SS_SMEM_FLOATS * sizeof(float)>>>(
            Qp, Kp, mask, attn);
    }

    // attn @ V  (fp16 O)
    {
        dim3 ga(Nq / 64, Bz * Hh);
        av_kernel<<<ga, 256>>>(attn, Vp, hO);
    }

    // Output projection + bias (fp16 mma.sync)
    {
        dim3 go(Cd / 128, (Bz * Nq) / 128);      // 8 x 16
        gemm_f16_mma<<<go, 256, GEMM_SMEM>>>(hO, w3, bp, out, Cd, Cd);
    }
}

// round 8
// speedup vs baseline: 2.5282x; 1.1135x over previous
#include <cuda_runtime.h>
#include <cuda_fp16.h>
#include <math.h>
#include <stdint.h>

// Problem constants
constexpr int Bz = 8;
constexpr int Nq = 256;
constexpr int Mc = 1024;
constexpr int Cd = 1024;
constexpr int Hh = 16;

// Scratch
__device__ float  g_Q[Bz * Nq * Cd];    // Q proj (fp32)
__device__ float  g_K[Bz * Mc * Cd];    // K proj (fp32)
__device__ __half g_hQ[Bz * Nq * Cd];   // LN(q) fp16
__device__ __half g_hK[Bz * Mc * Cd];   // LN(k) fp16
__device__ __half g_hV[Bz * Mc * Cd];   // V proj fp16
__device__ __half g_hO[Bz * Nq * Cd];   // AV out fp16
__device__ __half g_hq[Bz * Nq * Cd];   // query fp16
__device__ __half g_hc[Bz * Mc * Cd];   // context fp16
__device__ __half g_w0[Cd * Cd];        // Wq fp16
__device__ __half g_w1[Cd * Cd];        // Wk fp16
__device__ __half g_w2[Cd * Cd];        // Wv fp16
__device__ __half g_w3[Cd * Cd];        // Wp fp16

// ---------------------------------------------------------------------------
// PTX helpers (legacy path only — build rejects sm_103a-only features)
// ---------------------------------------------------------------------------
__device__ __forceinline__ void cp_async16(uint32_t saddr, const void* gptr) {
    asm volatile("cp.async.ca.shared.global [%0], [%1], 16;" ::
                 "r"(saddr), "l"(gptr));
}
__device__ __forceinline__ void cp_commit() { asm volatile("cp.async.commit_group;"); }
__device__ __forceinline__ void cp_wait0()  { asm volatile("cp.async.wait_group 0;"); }

__device__ __forceinline__ void mma_f16_16816(float c[4], uint32_t a0, uint32_t a1,
                                              uint32_t a2, uint32_t a3,
                                              uint32_t b0, uint32_t b1) {
    asm volatile(
        "mma.sync.aligned.m16n8k16.row.col.f32.f16.f16.f32 "
        "{%0,%1,%2,%3}, {%4,%5,%6,%7}, {%8,%9}, {%0,%1,%2,%3};"
        : "+f"(c[0]), "+f"(c[1]), "+f"(c[2]), "+f"(c[3])
        : "r"(a0), "r"(a1), "r"(a2), "r"(a3), "r"(b0), "r"(b1));
}

__device__ __forceinline__ uint32_t h2u(__half2 h) {
    return *reinterpret_cast<uint32_t*>(&h);
}

// ---------------------------------------------------------------------------
// fp32 -> fp16 conversion
// ---------------------------------------------------------------------------
__global__ void cvt_f16_kernel(const float* __restrict__ in,
                               __half* __restrict__ out, int n4) {
    int i = blockIdx.x * blockDim.x + threadIdx.x;
    if (i >= n4) return;
    float4 v = ((const float4*)in)[i];
    ((__half2*)out)[2 * i]     = __floats2half2_rn(v.x, v.y);
    ((__half2*)out)[2 * i + 1] = __floats2half2_rn(v.z, v.w);
}

// ---------------------------------------------------------------------------
// FP16 mma.sync GEMM: C = A[Ma,K] * B[Nb,K]^T (+bias). fp32 out (Cc) or
// fp16 out (Ch) when Ch != nullptr. 128x128 CTA, 8 warps, kTile=64.
// ---------------------------------------------------------------------------
constexpr int GEMM_SMEM = 2 * 2 * 128 * 72 * 2;  // 73728 bytes

__global__ __launch_bounds__(256, 2)
void gemm_f16_mma(const __half* __restrict__ A, const __half* __restrict__ Bw,
                  const float* __restrict__ bias, float* __restrict__ Cc,
                  __half* __restrict__ Ch, int Nb, int K) {
    extern __shared__ __half smh[];
    __half* As = smh;                   // [2][128][72]
    __half* Bs = smh + 2 * 128 * 72;    // [2][128][72]

    const int tid  = threadIdx.x;
    const int lane = tid & 31;
    const int w    = tid >> 5;
    const int wm   = (w & 1) * 64;
    const int wn   = (w >> 1) * 32;
    const int g    = lane >> 2;
    const int ti   = lane & 3;
    const int brow = blockIdx.y * 128;
    const int bcol = blockIdx.x * 128;

    const int lrow = tid >> 1;
    const int lh   = (tid & 1) * 32;
    const __half* Ag = A  + (size_t)(brow + lrow) * K + lh;
    const __half* Bg = Bw + (size_t)(bcol + lrow) * K + lh;
    const uint32_t sa = (uint32_t)__cvta_generic_to_shared(&As[lrow * 72 + lh]);
    const uint32_t sb = (uint32_t)__cvta_generic_to_shared(&Bs[lrow * 72 + lh]);
    const uint32_t stageB = 128 * 72 * 2;

    float c[4][4][4];
#pragma unroll
    for (int mt = 0; mt < 4; mt++)
#pragma unroll
        for (int nt = 0; nt < 4; nt++)
#pragma unroll
            for (int e = 0; e < 4; e++) c[mt][nt][e] = 0.f;

    const int niter = K / 64;

#pragma unroll
    for (int v = 0; v < 4; v++) {
        cp_async16(sa + v * 16, Ag + v * 8);
        cp_async16(sb + v * 16, Bg + v * 8);
    }
    cp_commit();
    cp_wait0();
    __syncthreads();

    for (int t = 0; t < niter; t++) {
        if (t + 1 < niter) {
            const int k0 = (t + 1) * 64;
            const uint32_t so = ((t + 1) & 1) * stageB;
#pragma unroll
            for (int v = 0; v < 4; v++) {
                cp_async16(sa + so + v * 16, Ag + k0 + v * 8);
                cp_async16(sb + so + v * 16, Bg + k0 + v * 8);
            }
            cp_commit();
        }

        const __half* as = As + (t & 1) * 128 * 72;
        const __half* bs = Bs + (t & 1) * 128 * 72;

#pragma unroll
        for (int ks = 0; ks < 4; ks++) {
            const int kk = ks * 16;
            uint32_t a[4][4], b[4][2];
#pragma unroll
            for (int mt = 0; mt < 4; mt++) {
                const int r0 = wm + mt * 16 + g;
                a[mt][0] = *(const uint32_t*)&as[r0 * 72 + kk + 2 * ti];
                a[mt][1] = *(const uint32_t*)&as[(r0 + 8) * 72 + kk + 2 * ti];
                a[mt][2] = *(const uint32_t*)&as[r0 * 72 + kk + 2 * ti + 8];
                a[mt][3] = *(const uint32_t*)&as[(r0 + 8) * 72 + kk + 2 * ti + 8];
            }
#pragma unroll
            for (int nt = 0; nt < 4; nt++) {
                const int n0 = wn + nt * 8 + g;
                b[nt][0] = *(const uint32_t*)&bs[n0 * 72 + kk + 2 * ti];
                b[nt][1] = *(const uint32_t*)&bs[n0 * 72 + kk + 2 * ti + 8];
            }
#pragma unroll
            for (int mt = 0; mt < 4; mt++)
#pragma unroll
                for (int nt = 0; nt < 4; nt++)
                    mma_f16_16816(c[mt][nt], a[mt][0], a[mt][1], a[mt][2],
                                  a[mt][3], b[nt][0], b[nt][1]);
        }

        if (t + 1 < niter) {
            cp_wait0();
            __syncthreads();
        }
    }

#pragma unroll
    for (int mt = 0; mt < 4; mt++) {
#pragma unroll
        for (int nt = 0; nt < 4; nt++) {
            const int row0 = brow + wm + mt * 16 + g;
            const int col0 = bcol + wn + nt * 8 + 2 * ti;
            float b0 = 0.f, b1 = 0.f;
            if (bias != nullptr) { b0 = bias[col0]; b1 = bias[col0 + 1]; }
            if (Ch != nullptr) {
                *(__half2*)(Ch + (size_t)row0 * Nb + col0) =
                    __floats2half2_rn(c[mt][nt][0] + b0, c[mt][nt][1] + b1);
                *(__half2*)(Ch + (size_t)(row0 + 8) * Nb + col0) =
                    __floats2half2_rn(c[mt][nt][2] + b0, c[mt][nt][3] + b1);
            } else {
                *(float2*)(Cc + (size_t)row0 * Nb + col0) =
                    make_float2(c[mt][nt][0] + b0, c[mt][nt][1] + b1);
                *(float2*)(Cc + (size_t)(row0 + 8) * Nb + col0) =
                    make_float2(c[mt][nt][2] + b0, c[mt][nt][3] + b1);
            }
        }
    }
}

// ---------------------------------------------------------------------------
// LayerNorm over 64-element groups: fp32 in, fp16 out (one warp per group)
// ---------------------------------------------------------------------------
__global__ void ln64_f16_kernel(const float* __restrict__ X,
                                const float* __restrict__ gamma,
                                const float* __restrict__ beta,
                                __half* __restrict__ Y, int ngroups) {
    const int warp = (blockIdx.x * blockDim.x + threadIdx.x) >> 5;
    const int lane = threadIdx.x & 31;
    if (warp >= ngroups) return;
    const float* x = X + (size_t)warp * 64;
    float x0 = x[lane];
    float x1 = x[lane + 32];
    float s  = x0 + x1;
    float sq = x0 * x0 + x1 * x1;
#pragma unroll
    for (int o = 16; o > 0; o >>= 1) {
        s  += __shfl_xor_sync(0xFFFFFFFFu, s, o);
        sq += __shfl_xor_sync(0xFFFFFFFFu, sq, o);
    }
    const float mean = s * (1.f / 64.f);
    const float var  = sq * (1.f / 64.f) - mean * mean;
    const float rstd = rsqrtf(var + 1e-5f);
    __half* y = Y + (size_t)warp * 64;
    y[lane]      = __float2half_rn((x0 - mean) * rstd * gamma[lane]      + beta[lane]);
    y[lane + 32] = __float2half_rn((x1 - mean) * rstd * gamma[lane + 32] + beta[lane + 32]);
}

// ---------------------------------------------------------------------------
// Fused attention: scores (fp16 mma) + mask + softmax + AV (fp16 mma).
// Block = 32 q-rows x one (b,h); 256 threads (8 warps).
// smem: S[32][1024] f32, Qh[32][72] f16, KVt[64][72] f16 (K chunk / V^T)
// ---------------------------------------------------------------------------
constexpr int ATT_SMEM = 32 * 1024 * 4 + 32 * 72 * 2 + 64 * 72 * 2;  // 144896 B

__global__ __launch_bounds__(256)
void attention_kernel(const __half* __restrict__ Qh16, const __half* __restrict__ Kh16,
                      const __half* __restrict__ Vh16, const int* __restrict__ mask,
                      float* __restrict__ attn, __half* __restrict__ O) {
    extern __shared__ char smraw[];
    float*  S   = (float*)smraw;                          // [32][1024]
    __half* Qh  = (__half*)(smraw + 32 * 1024 * 4);       // [32][72]
    __half* KVt = (__half*)(smraw + 32 * 1024 * 4 + 32 * 72 * 2);  // [64][72]

    const int bh = blockIdx.y;
    const int b  = bh >> 4;
    const int h  = bh & 15;
    const int n0 = blockIdx.x * 32;
    const int tid  = threadIdx.x;
    const int lane = tid & 31;
    const int w    = tid >> 5;
    const int g    = lane >> 2;
    const int ti   = lane & 3;

    // ---- load Q tile [32 n][64 d] fp16 ----
    {
        const int n  = tid >> 3;
        const int d0 = (tid & 7) * 8;
        const __half* qp = Qh16 + (size_t)(b * Nq + n0 + n) * Cd + h * 64 + d0;
        *(uint4*)&Qh[n * 72 + d0] = *(const uint4*)qp;
    }

    // ---- pass 1: scores ----
    const float scale = 0.125f;
    for (int mc = 0; mc < Mc; mc += 64) {
        {
            const int m  = tid >> 2;
            const int d0 = (tid & 3) * 16;
            const __half* kp = Kh16 + (size_t)(b * Mc + mc + m) * Cd + h * 64 + d0;
            *(uint4*)&KVt[m * 72 + d0]     = *(const uint4*)kp;
            *(uint4*)&KVt[m * 72 + d0 + 8] = *(const uint4*)(kp + 8);
        }
        __syncthreads();

        float c[2][4];
#pragma unroll
        for (int mt = 0; mt < 2; mt++)
#pragma unroll
            for (int e = 0; e < 4; e++) c[mt][e] = 0.f;

#pragma unroll
        for (int ks = 0; ks < 4; ks++) {
            const int kk = ks * 16;
            uint32_t a[2][4], bb[2];
#pragma unroll
            for (int mt = 0; mt < 2; mt++) {
                const int r0 = mt * 16 + g;
                a[mt][0] = *(const uint32_t*)&Qh[r0 * 72 + kk + 2 * ti];
                a[mt][1] = *(const uint32_t*)&Qh[(r0 + 8) * 72 + kk + 2 * ti];
                a[mt][2] = *(const uint32_t*)&Qh[r0 * 72 + kk + 2 * ti + 8];
                a[mt][3] = *(const uint32_t*)&Qh[(r0 + 8) * 72 + kk + 2 * ti + 8];
            }
            const int mrow = w * 8 + g;  // chunk-local m
            bb[0] = *(const uint32_t*)&KVt[mrow * 72 + kk + 2 * ti];
            bb[1] = *(const uint32_t*)&KVt[mrow * 72 + kk + 2 * ti + 8];
#pragma unroll
            for (int mt = 0; mt < 2; mt++)
                mma_f16_16816(c[mt], a[mt][0], a[mt][1], a[mt][2], a[mt][3],
                              bb[0], bb[1]);
        }

        // scale + mask + store to S
        const int m0 = mc + w * 8 + 2 * ti;
        const bool ok0 = mask[b * Mc + m0] != 0;
        const bool ok1 = mask[b * Mc + m0 + 1] != 0;
#pragma unroll
        for (int mt = 0; mt < 2; mt++) {
            const int r = mt * 16 + g;
            S[r * 1024 + m0]            = ok0 ? c[mt][0] * scale : -1e30f;
            S[r * 1024 + m0 + 1]        = ok1 ? c[mt][1] * scale : -1e30f;
            S[(r + 8) * 1024 + m0]      = ok0 ? c[mt][2] * scale : -1e30f;
            S[(r + 8) * 1024 + m0 + 1]  = ok1 ? c[mt][3] * scale : -1e30f;
        }
        __syncthreads();
    }

    // ---- pass 2: softmax in S, write attn (fp32) + normalized back to S ----
    for (int r = 0; r < 4; r++) {
        const int n = w * 4 + r;
        float* p = S + (size_t)n * 1024;

        float4 v[8];
        float mx = -1e30f;
#pragma unroll
        for (int i = 0; i < 8; i++) {
            v[i] = *(const float4*)(p + (i * 32 + lane) * 4);
            mx = fmaxf(mx, fmaxf(fmaxf(v[i].x, v[i].y), fmaxf(v[i].z, v[i].w)));
        }
#pragma unroll
        for (int o = 16; o > 0; o >>= 1) mx = fmaxf(mx, __shfl_xor_sync(0xFFFFFFFFu, mx, o));

        float sum = 0.f;
#pragma unroll
        for (int i = 0; i < 8; i++) {
            v[i].x = __expf(v[i].x - mx);
            v[i].y = __expf(v[i].y - mx);
            v[i].z = __expf(v[i].z - mx);
            v[i].w = __expf(v[i].w - mx);
            sum += v[i].x + v[i].y + v[i].z + v[i].w;
        }
#pragma unroll
        for (int o = 16; o > 0; o >>= 1) sum += __shfl_xor_sync(0xFFFFFFFFu, sum, o);
        const float inv = 1.f / sum;

        float* op = attn + ((size_t)bh * Nq + n0 + n) * Mc;
#pragma unroll
        for (int i = 0; i < 8; i++) {
            v[i].x *= inv; v[i].y *= inv; v[i].z *= inv; v[i].w *= inv;
            *(float4*)(op + (i * 32 + lane) * 4) = v[i];
            *(float4*)(p + (i * 32 + lane) * 4)  = v[i];
        }
    }
    __syncthreads();

    // ---- pass 3: AV (fp16 mma). warp w owns d-slab [w*8, w*8+8) ----
    float o2[2][4];
#pragma unroll
    for (int mt = 0; mt < 2; mt++)
#pragma unroll
        for (int e = 0; e < 4; e++) o2[mt][e] = 0.f;

    for (int mc = 0; mc < Mc; mc += 64) {
        // load V chunk [64 m][64 d] -> transpose into KVt[d][m]
        {
            const int m  = tid >> 2;
            const int d0 = (tid & 3) * 16;
            const __half* vp = Vh16 + (size_t)(b * Mc + mc + m) * Cd + h * 64 + d0;
            uint4 v0 = *(const uint4*)vp;
            uint4 v1 = *(const uint4*)(vp + 8);
            const __half* h0 = (const __half*)&v0;
            const __half* h1 = (const __half*)&v1;
#pragma unroll
            for (int i = 0; i < 8; i++) KVt[(d0 + i) * 72 + m]     = h0[i];
#pragma unroll
            for (int i = 0; i < 8; i++) KVt[(d0 + 8 + i) * 72 + m] = h1[i];
        }
        __syncthreads();

#pragma unroll
        for (int ks = 0; ks < 4; ks++) {
            const int kk = ks * 16;
            uint32_t a[2][4], bb[2];
#pragma unroll
            for (int mt = 0; mt < 2; mt++) {
                const int r0 = mt * 16 + g;
                float2 f0 = *(const float2*)&S[r0 * 1024 + mc + kk + 2 * ti];
                float2 f1 = *(const float2*)&S[(r0 + 8) * 1024 + mc + kk + 2 * ti];
                float2 f2 = *(const float2*)&S[r0 * 1024 + mc + kk + 2 * ti + 8];
                float2 f3 = *(const float2*)&S[(r0 + 8) * 1024 + mc + kk + 2 * ti + 8];
                a[mt][0] = h2u(__floats2half2_rn(f0.x, f0.y));
                a[mt][1] = h2u(__floats2half2_rn(f1.x, f1.y));
                a[mt][2] = h2u(__floats2half2_rn(f2.x, f2.y));
                a[mt][3] = h2u(__floats2half2_rn(f3.x, f3.y));
            }
            const int drow = w * 8 + g;
            bb[0] = *(const uint32_t*)&KVt[drow * 72 + kk + 2 * ti];
            bb[1] = *(const uint32_t*)&KVt[drow * 72 + kk + 2 * ti + 8];
#pragma unroll
            for (int mt = 0; mt < 2; mt++)
                mma_f16_16816(o2[mt], a[mt][0], a[mt][1], a[mt][2], a[mt][3],
                              bb[0], bb[1]);
        }
        __syncthreads();
    }

    // write O fp16: rows n = mt*16+g (+8), cols d = h*64 + w*8 + 2ti (+1)
#pragma unroll
    for (int mt = 0; mt < 2; mt++) {
        const int r = mt * 16 + g;
        const int col = h * 64 + w * 8 + 2 * ti;
        *(__half2*)(O + (size_t)(b * Nq + n0 + r) * Cd + col) =
            __floats2half2_rn(o2[mt][0], o2[mt][1]);
        *(__half2*)(O + (size_t)(b * Nq + n0 + r + 8) * Cd + col) =
            __floats2half2_rn(o2[mt][2], o2[mt][3]);
    }
}

// ---------------------------------------------------------------------------
// Launch
// ---------------------------------------------------------------------------
extern "C" void kernel_launch(void* const* d_in, const int* in_sizes, int n_in,
                              void* d_out, int out_size) {
    const float* query   = (const float*)d_in[0];
    const float* context = (const float*)d_in[1];
    const int*   mask    = (const int*)d_in[2];
    const float* Wq      = (const float*)d_in[3];
    const float* Wk      = (const float*)d_in[4];
    const float* Wv      = (const float*)d_in[5];
    const float* qg      = (const float*)d_in[6];
    const float* qb      = (const float*)d_in[7];
    const float* kg      = (const float*)d_in[8];
    const float* kb      = (const float*)d_in[9];
    const float* Wp      = (const float*)d_in[10];
    const float* bp      = (const float*)d_in[11];

    float* out  = (float*)d_out;                 // [B,N,C]
    float* attn = out + (size_t)Bz * Nq * Cd;    // [B,H,N,M]

    float *Qp, *Kp;
    __half *hQ, *hK, *hV, *hO, *hq, *hc, *w0, *w1, *w2, *w3;
    cudaGetSymbolAddress((void**)&Qp, g_Q);
    cudaGetSymbolAddress((void**)&Kp, g_K);
    cudaGetSymbolAddress((void**)&hQ, g_hQ);
    cudaGetSymbolAddress((void**)&hK, g_hK);
    cudaGetSymbolAddress((void**)&hV, g_hV);
    cudaGetSymbolAddress((void**)&hO, g_hO);
    cudaGetSymbolAddress((void**)&hq, g_hq);
    cudaGetSymbolAddress((void**)&hc, g_hc);
    cudaGetSymbolAddress((void**)&w0, g_w0);
    cudaGetSymbolAddress((void**)&w1, g_w1);
    cudaGetSymbolAddress((void**)&w2, g_w2);
    cudaGetSymbolAddress((void**)&w3, g_w3);

    cudaFuncSetAttribute(gemm_f16_mma,
                         cudaFuncAttributeMaxDynamicSharedMemorySize, GEMM_SMEM);
    cudaFuncSetAttribute(attention_kernel,
                         cudaFuncAttributeMaxDynamicSharedMemorySize, ATT_SMEM);

    // fp16 pre-conversion
    {
        const int nQ = Bz * Nq * Cd / 4, nC = Bz * Mc * Cd / 4, nW = Cd * Cd / 4;
        cvt_f16_kernel<<<(nQ + 255) / 256, 256>>>(query, hq, nQ);
        cvt_f16_kernel<<<(nC + 255) / 256, 256>>>(context, hc, nC);
        cvt_f16_kernel<<<(nW + 255) / 256, 256>>>(Wq, w0, nW);
        cvt_f16_kernel<<<(nW + 255) / 256, 256>>>(Wk, w1, nW);
        cvt_f16_kernel<<<(nW + 255) / 256, 256>>>(Wv, w2, nW);
        cvt_f16_kernel<<<(nW + 255) / 256, 256>>>(Wp, w3, nW);
    }

    // Projections: Q,K -> fp32 (LN precision); V -> fp16 direct
    {
        dim3 gq(Cd / 128, (Bz * Nq) / 128);
        gemm_f16_mma<<<gq, 256, GEMM_SMEM>>>(hq, w0, nullptr, Qp, nullptr, Cd, Cd);
        dim3 gk(Cd / 128, (Bz * Mc) / 128);
        gemm_f16_mma<<<gk, 256, GEMM_SMEM>>>(hc, w1, nullptr, Kp, nullptr, Cd, Cd);
        gemm_f16_mma<<<gk, 256, GEMM_SMEM>>>(hc, w2, nullptr, nullptr, hV, Cd, Cd);
    }

    // LayerNorm q, k -> fp16
    {
        const int gq = Bz * Nq * Hh;
        const int gk = Bz * Mc * Hh;
        ln64_f16_kernel<<<(gq * 32 + 255) / 256, 256>>>(Qp, qg, qb, hQ, gq);
        ln64_f16_kernel<<<(gk * 32 + 255) / 256, 256>>>(Kp, kg, kb, hK, gk);
    }

    // Fused attention (scores + mask + softmax + AV)
    {
        dim3 ga(Nq / 32, Bz * Hh);               // 8 x 128
        attention_kernel<<<ga, 256, ATT_SMEM>>>(hQ, hK, hV, mask, attn, hO);
    }

    // Output projection + bias
    {
        dim3 go(Cd / 128, (Bz * Nq) / 128);
        gemm_f16_mma<<<go, 256, GEMM_SMEM>>>(hO, w3, bp, out, nullptr, Cd, Cd);
    }
}

// round 9
// speedup vs baseline: 3.9446x; 1.5602x over previous
#include <cuda_runtime.h>
#include <cuda_fp16.h>
#include <math.h>
#include <stdint.h>

// Problem constants
constexpr int Bz = 8;
constexpr int Nq = 256;
constexpr int Mc = 1024;
constexpr int Cd = 1024;
constexpr int Hh = 16;

// Scratch
__device__ float  g_Q[Bz * Nq * Cd];    // Q proj (fp32)
__device__ float  g_K[Bz * Mc * Cd];    // K proj (fp32)
__device__ __half g_hQ[Bz * Nq * Cd];   // LN(q) fp16
__device__ __half g_hK[Bz * Mc * Cd];   // LN(k) fp16
__device__ __half g_hV[Bz * Mc * Cd];   // V proj fp16
__device__ __half g_hO[Bz * Nq * Cd];   // AV out fp16
__device__ __half g_hq[Bz * Nq * Cd];   // query fp16
__device__ __half g_hc[Bz * Mc * Cd];   // context fp16
__device__ __half g_w0[Cd * Cd];
__device__ __half g_w1[Cd * Cd];
__device__ __half g_w2[Cd * Cd];
__device__ __half g_w3[Cd * Cd];

// ---------------------------------------------------------------------------
// PTX helpers
// ---------------------------------------------------------------------------
__device__ __forceinline__ void cp_async16(uint32_t saddr, const void* gptr) {
    asm volatile("cp.async.ca.shared.global [%0], [%1], 16;" ::
                 "r"(saddr), "l"(gptr));
}
__device__ __forceinline__ void cp_commit() { asm volatile("cp.async.commit_group;"); }
__device__ __forceinline__ void cp_wait0()  { asm volatile("cp.async.wait_group 0;"); }
__device__ __forceinline__ void cp_wait1()  { asm volatile("cp.async.wait_group 1;"); }

__device__ __forceinline__ void mma_f16_16816(float c[4], uint32_t a0, uint32_t a1,
                                              uint32_t a2, uint32_t a3,
                                              uint32_t b0, uint32_t b1) {
    asm volatile(
        "mma.sync.aligned.m16n8k16.row.col.f32.f16.f16.f32 "
        "{%0,%1,%2,%3}, {%4,%5,%6,%7}, {%8,%9}, {%0,%1,%2,%3};"
        : "+f"(c[0]), "+f"(c[1]), "+f"(c[2]), "+f"(c[3])
        : "r"(a0), "r"(a1), "r"(a2), "r"(a3), "r"(b0), "r"(b1));
}
__device__ __forceinline__ void ldsm_x4(uint32_t& r0, uint32_t& r1, uint32_t& r2,
                                        uint32_t& r3, uint32_t addr) {
    asm volatile("ldmatrix.sync.aligned.m8n8.x4.shared.b16 {%0,%1,%2,%3}, [%4];"
                 : "=r"(r0), "=r"(r1), "=r"(r2), "=r"(r3) : "r"(addr));
}
__device__ __forceinline__ void ldsm_x2(uint32_t& r0, uint32_t& r1, uint32_t addr) {
    asm volatile("ldmatrix.sync.aligned.m8n8.x2.shared.b16 {%0,%1}, [%2];"
                 : "=r"(r0), "=r"(r1) : "r"(addr));
}
__device__ __forceinline__ void ldsm_x2t(uint32_t& r0, uint32_t& r1, uint32_t addr) {
    asm volatile("ldmatrix.sync.aligned.m8n8.x2.trans.shared.b16 {%0,%1}, [%2];"
                 : "=r"(r0), "=r"(r1) : "r"(addr));
}
__device__ __forceinline__ uint32_t h2u(__half2 h) {
    return *reinterpret_cast<uint32_t*>(&h);
}

// ---------------------------------------------------------------------------
// fp32 -> fp16 conversion
// ---------------------------------------------------------------------------
__global__ void cvt_f16_kernel(const float* __restrict__ in,
                               __half* __restrict__ out, int n4) {
    int i = blockIdx.x * blockDim.x + threadIdx.x;
    if (i >= n4) return;
    float4 v = ((const float4*)in)[i];
    ((__half2*)out)[2 * i]     = __floats2half2_rn(v.x, v.y);
    ((__half2*)out)[2 * i + 1] = __floats2half2_rn(v.z, v.w);
}

// ---------------------------------------------------------------------------
// FP16 mma GEMM with ldmatrix fragments. C = A[Ma,K]*B[Nb,K]^T (+bias).
// 128x128 CTA, 8 warps (2m x 4n), kTile=64, 2-stage cp.async.
// ---------------------------------------------------------------------------
constexpr int GEMM_SMEM = 2 * 2 * 128 * 72 * 2;  // 73728 bytes

__global__ __launch_bounds__(256, 2)
void gemm_f16_mma(const __half* __restrict__ A, const __half* __restrict__ Bw,
                  const float* __restrict__ bias, float* __restrict__ Cc,
                  __half* __restrict__ Ch, int Nb, int K) {
    extern __shared__ __half smh[];
    __half* As = smh;                   // [2][128][72]
    __half* Bs = smh + 2 * 128 * 72;    // [2][128][72]

    const int tid  = threadIdx.x;
    const int lane = tid & 31;
    const int w    = tid >> 5;
    const int wm   = (w & 1) * 64;
    const int wn   = (w >> 1) * 32;
    const int g    = lane >> 2;
    const int ti   = lane & 3;
    const int lt   = lane >> 3;
    const int lr8  = lane & 7;
    const int brow = blockIdx.y * 128;
    const int bcol = blockIdx.x * 128;

    const int lrow = tid >> 1;
    const int lh   = (tid & 1) * 32;
    const __half* Ag = A  + (size_t)(brow + lrow) * K + lh;
    const __half* Bg = Bw + (size_t)(bcol + lrow) * K + lh;
    const uint32_t sa = (uint32_t)__cvta_generic_to_shared(&As[lrow * 72 + lh]);
    const uint32_t sb = (uint32_t)__cvta_generic_to_shared(&Bs[lrow * 72 + lh]);
    const uint32_t asBase = (uint32_t)__cvta_generic_to_shared(As);
    const uint32_t bsBase = (uint32_t)__cvta_generic_to_shared(Bs);
    const uint32_t stageB = 128 * 72 * 2;

    // per-lane ldmatrix offsets (bytes, within a stage)
    uint32_t aoff[4], boff[2];
#pragma unroll
    for (int mt = 0; mt < 4; mt++) {
        int row = wm + mt * 16 + ((lt & 1) << 3) + lr8;
        int col = (lt >> 1) << 3;
        aoff[mt] = (uint32_t)((row * 72 + col) * 2);
    }
#pragma unroll
    for (int p = 0; p < 2; p++) {
        int row = wn + p * 16 + ((lt >> 1) << 3) + lr8;
        int col = (lt & 1) << 3;
        boff[p] = (uint32_t)((row * 72 + col) * 2);
    }

    float c[4][4][4];
#pragma unroll
    for (int mt = 0; mt < 4; mt++)
#pragma unroll
        for (int nt = 0; nt < 4; nt++)
#pragma unroll
            for (int e = 0; e < 4; e++) c[mt][nt][e] = 0.f;

    const int niter = K / 64;

#pragma unroll
    for (int v = 0; v < 4; v++) {
        cp_async16(sa + v * 16, Ag + v * 8);
        cp_async16(sb + v * 16, Bg + v * 8);
    }
    cp_commit();
    cp_wait0();
    __syncthreads();

    for (int t = 0; t < niter; t++) {
        if (t + 1 < niter) {
            const int k0 = (t + 1) * 64;
            const uint32_t so = ((t + 1) & 1) * stageB;
#pragma unroll
            for (int v = 0; v < 4; v++) {
                cp_async16(sa + so + v * 16, Ag + k0 + v * 8);
                cp_async16(sb + so + v * 16, Bg + k0 + v * 8);
            }
            cp_commit();
        }

        const uint32_t so = (t & 1) * stageB;

#pragma unroll
        for (int ks = 0; ks < 4; ks++) {
            const uint32_t kk2 = ks * 32;  // 16 halves = 32 bytes
            uint32_t a[4][4], b[4][2];
#pragma unroll
            for (int mt = 0; mt < 4; mt++)
                ldsm_x4(a[mt][0], a[mt][1], a[mt][2], a[mt][3],
                        asBase + so + aoff[mt] + kk2);
#pragma unroll
            for (int p = 0; p < 2; p++)
                ldsm_x4(b[2 * p][0], b[2 * p][1], b[2 * p + 1][0], b[2 * p + 1][1],
                        bsBase + so + boff[p] + kk2);
#pragma unroll
            for (int mt = 0; mt < 4; mt++)
#pragma unroll
                for (int nt = 0; nt < 4; nt++)
                    mma_f16_16816(c[mt][nt], a[mt][0], a[mt][1], a[mt][2],
                                  a[mt][3], b[nt][0], b[nt][1]);
        }

        if (t + 1 < niter) {
            cp_wait0();
            __syncthreads();
        }
    }

#pragma unroll
    for (int mt = 0; mt < 4; mt++) {
#pragma unroll
        for (int nt = 0; nt < 4; nt++) {
            const int row0 = brow + wm + mt * 16 + g;
            const int col0 = bcol + wn + nt * 8 + 2 * ti;
            float b0 = 0.f, b1 = 0.f;
            if (bias != nullptr) { b0 = bias[col0]; b1 = bias[col0 + 1]; }
            if (Ch != nullptr) {
                *(__half2*)(Ch + (size_t)row0 * Nb + col0) =
                    __floats2half2_rn(c[mt][nt][0] + b0, c[mt][nt][1] + b1);
                *(__half2*)(Ch + (size_t)(row0 + 8) * Nb + col0) =
                    __floats2half2_rn(c[mt][nt][2] + b0, c[mt][nt][3] + b1);
            } else {
                *(float2*)(Cc + (size_t)row0 * Nb + col0) =
                    make_float2(c[mt][nt][0] + b0, c[mt][nt][1] + b1);
                *(float2*)(Cc + (size_t)(row0 + 8) * Nb + col0) =
                    make_float2(c[mt][nt][2] + b0, c[mt][nt][3] + b1);
            }
        }
    }
}

// ---------------------------------------------------------------------------
// LayerNorm over 64-element groups: fp32 in, fp16 out
// ---------------------------------------------------------------------------
__global__ void ln64_f16_kernel(const float* __restrict__ X,
                                const float* __restrict__ gamma,
                                const float* __restrict__ beta,
                                __half* __restrict__ Y, int ngroups) {
    const int warp = (blockIdx.x * blockDim.x + threadIdx.x) >> 5;
    const int lane = threadIdx.x & 31;
    if (warp >= ngroups) return;
    const float* x = X + (size_t)warp * 64;
    float x0 = x[lane];
    float x1 = x[lane + 32];
    float s  = x0 + x1;
    float sq = x0 * x0 + x1 * x1;
#pragma unroll
    for (int o = 16; o > 0; o >>= 1) {
        s  += __shfl_xor_sync(0xFFFFFFFFu, s, o);
        sq += __shfl_xor_sync(0xFFFFFFFFu, sq, o);
    }
    const float mean = s * (1.f / 64.f);
    const float var  = sq * (1.f / 64.f) - mean * mean;
    const float rstd = rsqrtf(var + 1e-5f);
    __half* y = Y + (size_t)warp * 64;
    y[lane]      = __float2half_rn((x0 - mean) * rstd * gamma[lane]      + beta[lane]);
    y[lane + 32] = __float2half_rn((x1 - mean) * rstd * gamma[lane + 32] + beta[lane + 32]);
}

// ---------------------------------------------------------------------------
// Fused attention: scores (mma, Q-frags hoisted) + softmax + AV (mma,
// ldmatrix.trans V). Double-buffered cp.async K/V staging.
// Block = 32 q-rows x one (b,h); 256 threads.
// ---------------------------------------------------------------------------
constexpr int SPITCH   = 1028;  // floats per S row (bank-stagger pad)
constexpr int ATT_SMEM = 32 * SPITCH * 4 + 32 * 72 * 2 + 2 * 64 * 72 * 2;  // 154624

__global__ __launch_bounds__(256)
void attention_kernel(const __half* __restrict__ Qh16, const __half* __restrict__ Kh16,
                      const __half* __restrict__ Vh16, const int* __restrict__ mask,
                      float* __restrict__ attn, __half* __restrict__ O) {
    extern __shared__ char smraw[];
    float*  S  = (float*)smraw;                                   // [32][SPITCH]
    __half* Qh = (__half*)(smraw + 32 * SPITCH * 4);              // [32][72]
    __half* KV = (__half*)(smraw + 32 * SPITCH * 4 + 32 * 72 * 2);// [2][64][72]

    const int bh = blockIdx.y;
    const int b  = bh >> 4;
    const int h  = bh & 15;
    const int n0 = blockIdx.x * 32;
    const int tid  = threadIdx.x;
    const int lane = tid & 31;
    const int w    = tid >> 5;
    const int g    = lane >> 2;
    const int ti   = lane & 3;
    const int lt   = lane >> 3;
    const int lr8  = lane & 7;
    const int l16  = lane & 15;

    const uint32_t sBase  = (uint32_t)__cvta_generic_to_shared(smraw);
    const uint32_t qBase  = (uint32_t)__cvta_generic_to_shared(Qh);
    const uint32_t kvBase = (uint32_t)__cvta_generic_to_shared(KV);
    const uint32_t bufB   = 64 * 72 * 2;  // 9216

    // ---- load Q tile [32 n][64 d] fp16 ----
    {
        const int n  = tid >> 3;
        const int d0 = (tid & 7) * 8;
        const __half* qp = Qh16 + (size_t)(b * Nq + n0 + n) * Cd + h * 64 + d0;
        *(uint4*)&Qh[n * 72 + d0] = *(const uint4*)qp;
    }
    __syncthreads();

    // ---- hoist Q fragments (loop-invariant over all 16 m-chunks) ----
    uint32_t qa[4][2][4];
#pragma unroll
    for (int mt = 0; mt < 2; mt++) {
        const uint32_t off = qBase +
            (uint32_t)(((mt * 16 + ((lt & 1) << 3) + lr8) * 72 + ((lt >> 1) << 3)) * 2);
#pragma unroll
        for (int ks = 0; ks < 4; ks++)
            ldsm_x4(qa[ks][mt][0], qa[ks][mt][1], qa[ks][mt][2], qa[ks][mt][3],
                    off + ks * 32);
    }

    // staging: each thread copies 32 bytes of one KV row
    const int   stM  = tid >> 2;
    const int   stD0 = (tid & 3) * 16;
    const uint32_t stDst = kvBase + (uint32_t)((stM * 72 + stD0) * 2);

    // ---- pass 1: scores ----
    const float scale = 0.125f;
    {
        const __half* kp0 = Kh16 + (size_t)(b * Mc + stM) * Cd + h * 64 + stD0;
        cp_async16(stDst, kp0);
        cp_async16(stDst + 16, kp0 + 8);
        cp_commit();
    }
    const uint32_t kboff = (uint32_t)(((w * 8 + (l16 & 7)) * 72 + ((l16 >> 3) << 3)) * 2);

    for (int j = 0; j < 16; j++) {
        if (j < 15) {
            const __half* kp = Kh16 + (size_t)(b * Mc + (j + 1) * 64 + stM) * Cd + h * 64 + stD0;
            const uint32_t dst = stDst + ((j + 1) & 1) * bufB;
            cp_async16(dst, kp);
            cp_async16(dst + 16, kp + 8);
            cp_commit();
            cp_wait1();
        } else {
            cp_wait0();
        }
        __syncthreads();

        float c[2][4];
#pragma unroll
        for (int mt = 0; mt < 2; mt++)
#pragma unroll
            for (int e = 0; e < 4; e++) c[mt][e] = 0.f;

        const uint32_t kb = kvBase + (j & 1) * bufB + kboff;
#pragma unroll
        for (int ks = 0; ks < 4; ks++) {
            uint32_t b0, b1;
            ldsm_x2(b0, b1, kb + ks * 32);
            mma_f16_16816(c[0], qa[ks][0][0], qa[ks][0][1], qa[ks][0][2],
                          qa[ks][0][3], b0, b1);
            mma_f16_16816(c[1], qa[ks][1][0], qa[ks][1][1], qa[ks][1][2],
                          qa[ks][1][3], b0, b1);
        }

        const int m0 = j * 64 + w * 8 + 2 * ti;
        const bool ok0 = mask[b * Mc + m0] != 0;
        const bool ok1 = mask[b * Mc + m0 + 1] != 0;
#pragma unroll
        for (int mt = 0; mt < 2; mt++) {
            const int r = mt * 16 + g;
            S[r * SPITCH + m0]           = ok0 ? c[mt][0] * scale : -1e30f;
            S[r * SPITCH + m0 + 1]       = ok1 ? c[mt][1] * scale : -1e30f;
            S[(r + 8) * SPITCH + m0]     = ok0 ? c[mt][2] * scale : -1e30f;
            S[(r + 8) * SPITCH + m0 + 1] = ok1 ? c[mt][3] * scale : -1e30f;
        }
        __syncthreads();
    }

    // ---- pass 2: softmax; write attn fp32 to gmem + fp16 in-place to S ----
    for (int r = 0; r < 4; r++) {
        const int n = w * 4 + r;
        float* p = S + (size_t)n * SPITCH;

        float4 v[8];
        float mx = -1e30f;
#pragma unroll
        for (int i = 0; i < 8; i++) {
            v[i] = *(const float4*)(p + (i * 32 + lane) * 4);
            mx = fmaxf(mx, fmaxf(fmaxf(v[i].x, v[i].y), fmaxf(v[i].z, v[i].w)));
        }
#pragma unroll
        for (int o = 16; o > 0; o >>= 1) mx = fmaxf(mx, __shfl_xor_sync(0xFFFFFFFFu, mx, o));

        float sum = 0.f;
#pragma unroll
        for (int i = 0; i < 8; i++) {
            v[i].x = __expf(v[i].x - mx);
            v[i].y = __expf(v[i].y - mx);
            v[i].z = __expf(v[i].z - mx);
            v[i].w = __expf(v[i].w - mx);
            sum += v[i].x + v[i].y + v[i].z + v[i].w;
        }
#pragma unroll
        for (int o = 16; o > 0; o >>= 1) sum += __shfl_xor_sync(0xFFFFFFFFu, sum, o);
        const float inv = 1.f / sum;

        float*  op = attn + ((size_t)bh * Nq + n0 + n) * Mc;
        __half* ph = (__half*)p;
#pragma unroll
        for (int i = 0; i < 8; i++) {
            const int m0 = (i * 32 + lane) * 4;
            v[i].x *= inv; v[i].y *= inv; v[i].z *= inv; v[i].w *= inv;
            *(float4*)(op + m0) = v[i];
            uint2 hp;
            hp.x = h2u(__floats2half2_rn(v[i].x, v[i].y));
            hp.y = h2u(__floats2half2_rn(v[i].z, v[i].w));
            *(uint2*)(ph + m0) = hp;
        }
    }
    __syncthreads();

    // ---- pass 3: AV. A-frags from fp16 S (ldmatrix), B = V via ldmatrix.trans ----
    uint32_t sfoff[2];
#pragma unroll
    for (int mt = 0; mt < 2; mt++) {
        const int row = mt * 16 + ((lt & 1) << 3) + lr8;
        sfoff[mt] = (uint32_t)(row * (SPITCH * 4) + (((lt >> 1) << 3)) * 2);
    }
    const uint32_t vboff = (uint32_t)((l16 * 72 + w * 8) * 2);

    float o2[2][4];
#pragma unroll
    for (int mt = 0; mt < 2; mt++)
#pragma unroll
        for (int e = 0; e < 4; e++) o2[mt][e] = 0.f;

    {
        const __half* vp0 = Vh16 + (size_t)(b * Mc + stM) * Cd + h * 64 + stD0;
        cp_async16(stDst, vp0);
        cp_async16(stDst + 16, vp0 + 8);
        cp_commit();
    }

    for (int j = 0; j < 16; j++) {
        if (j < 15) {
            const __half* vp = Vh16 + (size_t)(b * Mc + (j + 1) * 64 + stM) * Cd + h * 64 + stD0;
            const uint32_t dst = stDst + ((j + 1) & 1) * bufB;
            cp_async16(dst, vp);
            cp_async16(dst + 16, vp + 8);
            cp_commit();
            cp_wait1();
        } else {
            cp_wait0();
        }
        __syncthreads();

        const uint32_t vb = kvBase + (j & 1) * bufB + vboff;
#pragma unroll
        for (int ks = 0; ks < 4; ks++) {
            uint32_t a[2][4], b0, b1;
            const uint32_t colB = (uint32_t)((j * 64 + ks * 16) * 2);
#pragma unroll
            for (int mt = 0; mt < 2; mt++)
                ldsm_x4(a[mt][0], a[mt][1], a[mt][2], a[mt][3],
                        sBase + sfoff[mt] + colB);
            ldsm_x2t(b0, b1, vb + ks * 2304);   // 16 rows * 144 B
            mma_f16_16816(o2[0], a[0][0], a[0][1], a[0][2], a[0][3], b0, b1);
            mma_f16_16816(o2[1], a[1][0], a[1][1], a[1][2], a[1][3], b0, b1);
        }
        __syncthreads();
    }

    // write O fp16
#pragma unroll
    for (int mt = 0; mt < 2; mt++) {
        const int r = mt * 16 + g;
        const int col = h * 64 + w * 8 + 2 * ti;
        *(__half2*)(O + (size_t)(b * Nq + n0 + r) * Cd + col) =
            __floats2half2_rn(o2[mt][0], o2[mt][1]);
        *(__half2*)(O + (size_t)(b * Nq + n0 + r + 8) * Cd + col) =
            __floats2half2_rn(o2[mt][2], o2[mt][3]);
    }
}

// ---------------------------------------------------------------------------
// Launch
// ---------------------------------------------------------------------------
extern "C" void kernel_launch(void* const* d_in, const int* in_sizes, int n_in,
                              void* d_out, int out_size) {
    const float* query   = (const float*)d_in[0];
    const float* context = (const float*)d_in[1];
    const int*   mask    = (const int*)d_in[2];
    const float* Wq      = (const float*)d_in[3];
    const float* Wk      = (const float*)d_in[4];
    const float* Wv      = (const float*)d_in[5];
    const float* qg      = (const float*)d_in[6];
    const float* qb      = (const float*)d_in[7];
    const float* kg      = (const float*)d_in[8];
    const float* kb      = (const float*)d_in[9];
    const float* Wp      = (const float*)d_in[10];
    const float* bp      = (const float*)d_in[11];

    float* out  = (float*)d_out;
    float* attn = out + (size_t)Bz * Nq * Cd;

    float *Qp, *Kp;
    __half *hQ, *hK, *hV, *hO, *hq, *hc, *w0, *w1, *w2, *w3;
    cudaGetSymbolAddress((void**)&Qp, g_Q);
    cudaGetSymbolAddress((void**)&Kp, g_K);
    cudaGetSymbolAddress((void**)&hQ, g_hQ);
    cudaGetSymbolAddress((void**)&hK, g_hK);
    cudaGetSymbolAddress((void**)&hV, g_hV);
    cudaGetSymbolAddress((void**)&hO, g_hO);
    cudaGetSymbolAddress((void**)&hq, g_hq);
    cudaGetSymbolAddress((void**)&hc, g_hc);
    cudaGetSymbolAddress((void**)&w0, g_w0);
    cudaGetSymbolAddress((void**)&w1, g_w1);
    cudaGetSymbolAddress((void**)&w2, g_w2);
    cudaGetSymbolAddress((void**)&w3, g_w3);

    cudaFuncSetAttribute(gemm_f16_mma,
                         cudaFuncAttributeMaxDynamicSharedMemorySize, GEMM_SMEM);
    cudaFuncSetAttribute(attention_kernel,
                         cudaFuncAttributeMaxDynamicSharedMemorySize, ATT_SMEM);

    // fp16 pre-conversion
    {
        const int nQ = Bz * Nq * Cd / 4, nC = Bz * Mc * Cd / 4, nW = Cd * Cd / 4;
        cvt_f16_kernel<<<(nQ + 255) / 256, 256>>>(query, hq, nQ);
        cvt_f16_kernel<<<(nC + 255) / 256, 256>>>(context, hc, nC);
        cvt_f16_kernel<<<(nW + 255) / 256, 256>>>(Wq, w0, nW);
        cvt_f16_kernel<<<(nW + 255) / 256, 256>>>(Wk, w1, nW);
        cvt_f16_kernel<<<(nW + 255) / 256, 256>>>(Wv, w2, nW);
        cvt_f16_kernel<<<(nW + 255) / 256, 256>>>(Wp, w3, nW);
    }

    // Projections: Q,K -> fp32 (for LN); V -> fp16 direct
    {
        dim3 gq(Cd / 128, (Bz * Nq) / 128);
        gemm_f16_mma<<<gq, 256, GEMM_SMEM>>>(hq, w0, nullptr, Qp, nullptr, Cd, Cd);
        dim3 gk(Cd / 128, (Bz * Mc) / 128);
        gemm_f16_mma<<<gk, 256, GEMM_SMEM>>>(hc, w1, nullptr, Kp, nullptr, Cd, Cd);
        gemm_f16_mma<<<gk, 256, GEMM_SMEM>>>(hc, w2, nullptr, nullptr, hV, Cd, Cd);
    }

    // LayerNorm q, k -> fp16
    {
        const int gq = Bz * Nq * Hh;
        const int gk = Bz * Mc * Hh;
        ln64_f16_kernel<<<(gq * 32 + 255) / 256, 256>>>(Qp, qg, qb, hQ, gq);
        ln64_f16_kernel<<<(gk * 32 + 255) / 256, 256>>>(Kp, kg, kb, hK, gk);
    }

    // Fused attention
    {
        dim3 ga(Nq / 32, Bz * Hh);
        attention_kernel<<<ga, 256, ATT_SMEM>>>(hQ, hK, hV, mask, attn, hO);
    }

    // Output projection + bias
    {
        dim3 go(Cd / 128, (Bz * Nq) / 128);
        gemm_f16_mma<<<go, 256, GEMM_SMEM>>>(hO, w3, bp, out, nullptr, Cd, Cd);
    }
}

// round 10
// speedup vs baseline: 3.9476x; 1.0008x over previous
#include <cuda_runtime.h>
#include <cuda_fp16.h>
#include <math.h>
#include <stdint.h>

// Problem constants
constexpr int Bz = 8;
constexpr int Nq = 256;
constexpr int Mc = 1024;
constexpr int Cd = 1024;
constexpr int Hh = 16;

// Scratch (fp32 Q/K buffers eliminated — LN fused into GEMM epilogue)
__device__ __half g_hQ[Bz * Nq * Cd];   // LN(q) fp16
__device__ __half g_hK[Bz * Mc * Cd];   // LN(k) fp16
__device__ __half g_hV[Bz * Mc * Cd];   // V proj fp16
__device__ __half g_hO[Bz * Nq * Cd];   // AV out fp16
__device__ __half g_hq[Bz * Nq * Cd];   // query fp16
__device__ __half g_hc[Bz * Mc * Cd];   // context fp16
__device__ __half g_w0[Cd * Cd];
__device__ __half g_w1[Cd * Cd];
__device__ __half g_w2[Cd * Cd];
__device__ __half g_w3[Cd * Cd];

// ---------------------------------------------------------------------------
// PTX helpers
// ---------------------------------------------------------------------------
__device__ __forceinline__ void cp_async16(uint32_t saddr, const void* gptr) {
    asm volatile("cp.async.ca.shared.global [%0], [%1], 16;" ::
                 "r"(saddr), "l"(gptr));
}
__device__ __forceinline__ void cp_commit() { asm volatile("cp.async.commit_group;"); }
__device__ __forceinline__ void cp_wait0()  { asm volatile("cp.async.wait_group 0;"); }
__device__ __forceinline__ void cp_wait1()  { asm volatile("cp.async.wait_group 1;"); }

__device__ __forceinline__ void mma_f16_16816(float c[4], uint32_t a0, uint32_t a1,
                                              uint32_t a2, uint32_t a3,
                                              uint32_t b0, uint32_t b1) {
    asm volatile(
        "mma.sync.aligned.m16n8k16.row.col.f32.f16.f16.f32 "
        "{%0,%1,%2,%3}, {%4,%5,%6,%7}, {%8,%9}, {%0,%1,%2,%3};"
        : "+f"(c[0]), "+f"(c[1]), "+f"(c[2]), "+f"(c[3])
        : "r"(a0), "r"(a1), "r"(a2), "r"(a3), "r"(b0), "r"(b1));
}
__device__ __forceinline__ void ldsm_x4(uint32_t& r0, uint32_t& r1, uint32_t& r2,
                                        uint32_t& r3, uint32_t addr) {
    asm volatile("ldmatrix.sync.aligned.m8n8.x4.shared.b16 {%0,%1,%2,%3}, [%4];"
                 : "=r"(r0), "=r"(r1), "=r"(r2), "=r"(r3) : "r"(addr));
}
__device__ __forceinline__ void ldsm_x2(uint32_t& r0, uint32_t& r1, uint32_t addr) {
    asm volatile("ldmatrix.sync.aligned.m8n8.x2.shared.b16 {%0,%1}, [%2];"
                 : "=r"(r0), "=r"(r1) : "r"(addr));
}
__device__ __forceinline__ void ldsm_x2t(uint32_t& r0, uint32_t& r1, uint32_t addr) {
    asm volatile("ldmatrix.sync.aligned.m8n8.x2.trans.shared.b16 {%0,%1}, [%2];"
                 : "=r"(r0), "=r"(r1) : "r"(addr));
}
__device__ __forceinline__ uint32_t h2u(__half2 h) {
    return *reinterpret_cast<uint32_t*>(&h);
}

// ---------------------------------------------------------------------------
// Merged fp32->fp16 conversion: all 6 tensors in ONE launch
// ---------------------------------------------------------------------------
constexpr int CVT_NQ = Bz * Nq * Cd / 4;   // 524288
constexpr int CVT_NC = Bz * Mc * Cd / 4;   // 2097152
constexpr int CVT_NW = Cd * Cd / 4;        // 262144
constexpr int CVT_TOTAL = CVT_NQ + CVT_NC + 4 * CVT_NW;

__global__ void cvt_all_kernel(const float* __restrict__ q, const float* __restrict__ c,
                               const float* __restrict__ wq, const float* __restrict__ wk,
                               const float* __restrict__ wv, const float* __restrict__ wp,
                               __half* hq, __half* hc, __half* h0, __half* h1,
                               __half* h2, __half* h3) {
    int i = blockIdx.x * blockDim.x + threadIdx.x;
    if (i >= CVT_TOTAL) return;
    const float* in; __half* out; int off;
    if (i < CVT_NQ)                    { in = q;  out = hq; off = i; }
    else if (i < CVT_NQ + CVT_NC)      { in = c;  out = hc; off = i - CVT_NQ; }
    else {
        int j = i - CVT_NQ - CVT_NC;
        int seg = j / CVT_NW;
        off = j - seg * CVT_NW;
        in  = (seg == 0) ? wq : (seg == 1) ? wk : (seg == 2) ? wv : wp;
        out = (seg == 0) ? h0 : (seg == 1) ? h1 : (seg == 2) ? h2 : h3;
    }
    float4 v = ((const float4*)in)[off];
    ((__half2*)out)[2 * off]     = __floats2half2_rn(v.x, v.y);
    ((__half2*)out)[2 * off + 1] = __floats2half2_rn(v.z, v.w);
}

// ---------------------------------------------------------------------------
// FP16 mma GEMM, ldmatrix fragments, kTile=64, 2-stage cp.async.
// Epilogues: gamma!=null -> per-64-col LayerNorm + fp16 out (Ch);
//            else Ch!=null -> fp16 out; else fp32 out (Cc) + bias.
// ---------------------------------------------------------------------------
constexpr int GEMM_SMEM = 2 * 2 * 128 * 72 * 2;  // 73728 bytes

__global__ __launch_bounds__(256, 2)
void gemm_f16_mma(const __half* __restrict__ A, const __half* __restrict__ Bw,
                  const float* __restrict__ bias, float* __restrict__ Cc,
                  __half* __restrict__ Ch, const float* __restrict__ gamma,
                  const float* __restrict__ beta, int Nb, int K) {
    extern __shared__ __half smh[];
    __half* As = smh;                   // [2][128][72]
    __half* Bs = smh + 2 * 128 * 72;    // [2][128][72]

    const int tid  = threadIdx.x;
    const int lane = tid & 31;
    const int w    = tid >> 5;
    const int wm   = (w & 1) * 64;
    const int wn   = (w >> 1) * 32;
    const int g    = lane >> 2;
    const int ti   = lane & 3;
    const int lt   = lane >> 3;
    const int lr8  = lane & 7;
    const int brow = blockIdx.y * 128;
    const int bcol = blockIdx.x * 128;

    const int lrow = tid >> 1;
    const int lh   = (tid & 1) * 32;
    const __half* Ag = A  + (size_t)(brow + lrow) * K + lh;
    const __half* Bg = Bw + (size_t)(bcol + lrow) * K + lh;
    const uint32_t sa = (uint32_t)__cvta_generic_to_shared(&As[lrow * 72 + lh]);
    const uint32_t sb = (uint32_t)__cvta_generic_to_shared(&Bs[lrow * 72 + lh]);
    const uint32_t asBase = (uint32_t)__cvta_generic_to_shared(As);
    const uint32_t bsBase = (uint32_t)__cvta_generic_to_shared(Bs);
    const uint32_t stageB = 128 * 72 * 2;

    uint32_t aoff[4], boff[2];
#pragma unroll
    for (int mt = 0; mt < 4; mt++) {
        int row = wm + mt * 16 + ((lt & 1) << 3) + lr8;
        int col = (lt >> 1) << 3;
        aoff[mt] = (uint32_t)((row * 72 + col) * 2);
    }
#pragma unroll
    for (int p = 0; p < 2; p++) {
        int row = wn + p * 16 + ((lt >> 1) << 3) + lr8;
        int col = (lt & 1) << 3;
        boff[p] = (uint32_t)((row * 72 + col) * 2);
    }

    float c[4][4][4];
#pragma unroll
    for (int mt = 0; mt < 4; mt++)
#pragma unroll
        for (int nt = 0; nt < 4; nt++)
#pragma unroll
            for (int e = 0; e < 4; e++) c[mt][nt][e] = 0.f;

    const int niter = K / 64;

#pragma unroll
    for (int v = 0; v < 4; v++) {
        cp_async16(sa + v * 16, Ag + v * 8);
        cp_async16(sb + v * 16, Bg + v * 8);
    }
    cp_commit();
    cp_wait0();
    __syncthreads();

    for (int t = 0; t < niter; t++) {
        if (t + 1 < niter) {
            const int k0 = (t + 1) * 64;
            const uint32_t so = ((t + 1) & 1) * stageB;
#pragma unroll
            for (int v = 0; v < 4; v++) {
                cp_async16(sa + so + v * 16, Ag + k0 + v * 8);
                cp_async16(sb + so + v * 16, Bg + k0 + v * 8);
            }
            cp_commit();
        }

        const uint32_t so = (t & 1) * stageB;

#pragma unroll
        for (int ks = 0; ks < 4; ks++) {
            const uint32_t kk2 = ks * 32;
            uint32_t a[4][4], b[4][2];
#pragma unroll
            for (int mt = 0; mt < 4; mt++)
                ldsm_x4(a[mt][0], a[mt][1], a[mt][2], a[mt][3],
                        asBase + so + aoff[mt] + kk2);
#pragma unroll
            for (int p = 0; p < 2; p++)
                ldsm_x4(b[2 * p][0], b[2 * p][1], b[2 * p + 1][0], b[2 * p + 1][1],
                        bsBase + so + boff[p] + kk2);
#pragma unroll
            for (int mt = 0; mt < 4; mt++)
#pragma unroll
                for (int nt = 0; nt < 4; nt++)
                    mma_f16_16816(c[mt][nt], a[mt][0], a[mt][1], a[mt][2],
                                  a[mt][3], b[nt][0], b[nt][1]);
        }

        if (t + 1 < niter) {
            cp_wait0();
            __syncthreads();
        }
    }

    if (gamma != nullptr) {
        // --- fused LayerNorm epilogue: stage tile, per-(row,64-group) LN ---
        __syncthreads();
        float* St = (float*)smh;   // [128][132] = 67584 B <= 73728
#pragma unroll
        for (int mt = 0; mt < 4; mt++)
#pragma unroll
            for (int nt = 0; nt < 4; nt++) {
                const int r0 = wm + mt * 16 + g;
                const int c0 = wn + nt * 8 + 2 * ti;
                *(float2*)&St[r0 * 132 + c0] =
                    make_float2(c[mt][nt][0], c[mt][nt][1]);
                *(float2*)&St[(r0 + 8) * 132 + c0] =
                    make_float2(c[mt][nt][2], c[mt][nt][3]);
            }
        __syncthreads();

        const int row = tid & 127;
        const int grp = tid >> 7;
        const float* pr = St + row * 132 + grp * 64;
        float s = 0.f, sq = 0.f;
#pragma unroll
        for (int i2 = 0; i2 < 16; i2++) {
            float4 v = *(const float4*)(pr + i2 * 4);
            s  += v.x + v.y + v.z + v.w;
            sq += v.x * v.x + v.y * v.y + v.z * v.z + v.w * v.w;
        }
        const float mean = s * (1.f / 64.f);
        const float var  = sq * (1.f / 64.f) - mean * mean;
        const float rstd = rsqrtf(var + 1e-5f);

        __half* yp = Ch + (size_t)(brow + row) * Nb + bcol + grp * 64;
#pragma unroll
        for (int i2 = 0; i2 < 16; i2++) {
            float4 v  = *(const float4*)(pr + i2 * 4);
            float4 gv = *(const float4*)(gamma + i2 * 4);
            float4 bv = *(const float4*)(beta + i2 * 4);
            *(__half2*)(yp + i2 * 4) =
                __floats2half2_rn((v.x - mean) * rstd * gv.x + bv.x,
                                  (v.y - mean) * rstd * gv.y + bv.y);
            *(__half2*)(yp + i2 * 4 + 2) =
                __floats2half2_rn((v.z - mean) * rstd * gv.z + bv.z,
                                  (v.w - mean) * rstd * gv.w + bv.w);
        }
        return;
    }

#pragma unroll
    for (int mt = 0; mt < 4; mt++) {
#pragma unroll
        for (int nt = 0; nt < 4; nt++) {
            const int row0 = brow + wm + mt * 16 + g;
            const int col0 = bcol + wn + nt * 8 + 2 * ti;
            float b0 = 0.f, b1 = 0.f;
            if (bias != nullptr) { b0 = bias[col0]; b1 = bias[col0 + 1]; }
            if (Ch != nullptr) {
                *(__half2*)(Ch + (size_t)row0 * Nb + col0) =
                    __floats2half2_rn(c[mt][nt][0] + b0, c[mt][nt][1] + b1);
                *(__half2*)(Ch + (size_t)(row0 + 8) * Nb + col0) =
                    __floats2half2_rn(c[mt][nt][2] + b0, c[mt][nt][3] + b1);
            } else {
                *(float2*)(Cc + (size_t)row0 * Nb + col0) =
                    make_float2(c[mt][nt][0] + b0, c[mt][nt][1] + b1);
                *(float2*)(Cc + (size_t)(row0 + 8) * Nb + col0) =
                    make_float2(c[mt][nt][2] + b0, c[mt][nt][3] + b1);
            }
        }
    }
}

// ---------------------------------------------------------------------------
// Fused attention (unchanged from R9): scores + softmax + AV.
// ---------------------------------------------------------------------------
constexpr int SPITCH   = 1028;
constexpr int ATT_SMEM = 32 * SPITCH * 4 + 32 * 72 * 2 + 2 * 64 * 72 * 2;  // 154624

__global__ __launch_bounds__(256)
void attention_kernel(const __half* __restrict__ Qh16, const __half* __restrict__ Kh16,
                      const __half* __restrict__ Vh16, const int* __restrict__ mask,
                      float* __restrict__ attn, __half* __restrict__ O) {
    extern __shared__ char smraw[];
    float*  S  = (float*)smraw;
    __half* Qh = (__half*)(smraw + 32 * SPITCH * 4);
    __half* KV = (__half*)(smraw + 32 * SPITCH * 4 + 32 * 72 * 2);

    const int bh = blockIdx.y;
    const int b  = bh >> 4;
    const int h  = bh & 15;
    const int n0 = blockIdx.x * 32;
    const int tid  = threadIdx.x;
    const int lane = tid & 31;
    const int w    = tid >> 5;
    const int g    = lane >> 2;
    const int ti   = lane & 3;
    const int lt   = lane >> 3;
    const int lr8  = lane & 7;
    const int l16  = lane & 15;

    const uint32_t sBase  = (uint32_t)__cvta_generic_to_shared(smraw);
    const uint32_t qBase  = (uint32_t)__cvta_generic_to_shared(Qh);
    const uint32_t kvBase = (uint32_t)__cvta_generic_to_shared(KV);
    const uint32_t bufB   = 64 * 72 * 2;

    {
        const int n  = tid >> 3;
        const int d0 = (tid & 7) * 8;
        const __half* qp = Qh16 + (size_t)(b * Nq + n0 + n) * Cd + h * 64 + d0;
        *(uint4*)&Qh[n * 72 + d0] = *(const uint4*)qp;
    }
    __syncthreads();

    uint32_t qa[4][2][4];
#pragma unroll
    for (int mt = 0; mt < 2; mt++) {
        const uint32_t off = qBase +
            (uint32_t)(((mt * 16 + ((lt & 1) << 3) + lr8) * 72 + ((lt >> 1) << 3)) * 2);
#pragma unroll
        for (int ks = 0; ks < 4; ks++)
            ldsm_x4(qa[ks][mt][0], qa[ks][mt][1], qa[ks][mt][2], qa[ks][mt][3],
                    off + ks * 32);
    }

    const int   stM  = tid >> 2;
    const int   stD0 = (tid & 3) * 16;
    const uint32_t stDst = kvBase + (uint32_t)((stM * 72 + stD0) * 2);

    const float scale = 0.125f;
    {
        const __half* kp0 = Kh16 + (size_t)(b * Mc + stM) * Cd + h * 64 + stD0;
        cp_async16(stDst, kp0);
        cp_async16(stDst + 16, kp0 + 8);
        cp_commit();
    }
    const uint32_t kboff = (uint32_t)(((w * 8 + (l16 & 7)) * 72 + ((l16 >> 3) << 3)) * 2);

    for (int j = 0; j < 16; j++) {
        if (j < 15) {
            const __half* kp = Kh16 + (size_t)(b * Mc + (j + 1) * 64 + stM) * Cd + h * 64 + stD0;
            const uint32_t dst = stDst + ((j + 1) & 1) * bufB;
            cp_async16(dst, kp);
            cp_async16(dst + 16, kp + 8);
            cp_commit();
            cp_wait1();
        } else {
            cp_wait0();
        }
        __syncthreads();

        float c[2][4];
#pragma unroll
        for (int mt = 0; mt < 2; mt++)
#pragma unroll
            for (int e = 0; e < 4; e++) c[mt][e] = 0.f;

        const uint32_t kb = kvBase + (j & 1) * bufB + kboff;
#pragma unroll
        for (int ks = 0; ks < 4; ks++) {
            uint32_t b0, b1;
            ldsm_x2(b0, b1, kb + ks * 32);
            mma_f16_16816(c[0], qa[ks][0][0], qa[ks][0][1], qa[ks][0][2],
                          qa[ks][0][3], b0, b1);
            mma_f16_16816(c[1], qa[ks][1][0], qa[ks][1][1], qa[ks][1][2],
                          qa[ks][1][3], b0, b1);
        }

        const int m0 = j * 64 + w * 8 + 2 * ti;
        const bool ok0 = mask[b * Mc + m0] != 0;
        const bool ok1 = mask[b * Mc + m0 + 1] != 0;
#pragma unroll
        for (int mt = 0; mt < 2; mt++) {
            const int r = mt * 16 + g;
            S[r * SPITCH + m0]           = ok0 ? c[mt][0] * scale : -1e30f;
            S[r * SPITCH + m0 + 1]       = ok1 ? c[mt][1] * scale : -1e30f;
            S[(r + 8) * SPITCH + m0]     = ok0 ? c[mt][2] * scale : -1e30f;
            S[(r + 8) * SPITCH + m0 + 1] = ok1 ? c[mt][3] * scale : -1e30f;
        }
        __syncthreads();
    }

    for (int r = 0; r < 4; r++) {
        const int n = w * 4 + r;
        float* p = S + (size_t)n * SPITCH;

        float4 v[8];
        float mx = -1e30f;
#pragma unroll
        for (int i = 0; i < 8; i++) {
            v[i] = *(const float4*)(p + (i * 32 + lane) * 4);
            mx = fmaxf(mx, fmaxf(fmaxf(v[i].x, v[i].y), fmaxf(v[i].z, v[i].w)));
        }
#pragma unroll
        for (int o = 16; o > 0; o >>= 1) mx = fmaxf(mx, __shfl_xor_sync(0xFFFFFFFFu, mx, o));

        float sum = 0.f;
#pragma unroll
        for (int i = 0; i < 8; i++) {
            v[i].x = __expf(v[i].x - mx);
            v[i].y = __expf(v[i].y - mx);
            v[i].z = __expf(v[i].z - mx);
            v[i].w = __expf(v[i].w - mx);
            sum += v[i].x + v[i].y + v[i].z + v[i].w;
        }
#pragma unroll
        for (int o = 16; o > 0; o >>= 1) sum += __shfl_xor_sync(0xFFFFFFFFu, sum, o);
        const float inv = 1.f / sum;

        float*  op = attn + ((size_t)bh * Nq + n0 + n) * Mc;
        __half* ph = (__half*)p;
#pragma unroll
        for (int i = 0; i < 8; i++) {
            const int m0 = (i * 32 + lane) * 4;
            v[i].x *= inv; v[i].y *= inv; v[i].z *= inv; v[i].w *= inv;
            *(float4*)(op + m0) = v[i];
            uint2 hp;
            hp.x = h2u(__floats2half2_rn(v[i].x, v[i].y));
            hp.y = h2u(__floats2half2_rn(v[i].z, v[i].w));
            *(uint2*)(ph + m0) = hp;
        }
    }
    __syncthreads();

    uint32_t sfoff[2];
#pragma unroll
    for (int mt = 0; mt < 2; mt++) {
        const int row = mt * 16 + ((lt & 1) << 3) + lr8;
        sfoff[mt] = (uint32_t)(row * (SPITCH * 4) + (((lt >> 1) << 3)) * 2);
    }
    const uint32_t vboff = (uint32_t)((l16 * 72 + w * 8) * 2);

    float o2[2][4];
#pragma unroll
    for (int mt = 0; mt < 2; mt++)
#pragma unroll
        for (int e = 0; e < 4; e++) o2[mt][e] = 0.f;

    {
        const __half* vp0 = Vh16 + (size_t)(b * Mc + stM) * Cd + h * 64 + stD0;
        cp_async16(stDst, vp0);
        cp_async16(stDst + 16, vp0 + 8);
        cp_commit();
    }

    for (int j = 0; j < 16; j++) {
        if (j < 15) {
            const __half* vp = Vh16 + (size_t)(b * Mc + (j + 1) * 64 + stM) * Cd + h * 64 + stD0;
            const uint32_t dst = stDst + ((j + 1) & 1) * bufB;
            cp_async16(dst, vp);
            cp_async16(dst + 16, vp + 8);
            cp_commit();
            cp_wait1();
        } else {
            cp_wait0();
        }
        __syncthreads();

        const uint32_t vb = kvBase + (j & 1) * bufB + vboff;
#pragma unroll
        for (int ks = 0; ks < 4; ks++) {
            uint32_t a[2][4], b0, b1;
            const uint32_t colB = (uint32_t)((j * 64 + ks * 16) * 2);
#pragma unroll
            for (int mt = 0; mt < 2; mt++)
                ldsm_x4(a[mt][0], a[mt][1], a[mt][2], a[mt][3],
                        sBase + sfoff[mt] + colB);
            ldsm_x2t(b0, b1, vb + ks * 2304);
            mma_f16_16816(o2[0], a[0][0], a[0][1], a[0][2], a[0][3], b0, b1);
            mma_f16_16816(o2[1], a[1][0], a[1][1], a[1][2], a[1][3], b0, b1);
        }
        __syncthreads();
    }

#pragma unroll
    for (int mt = 0; mt < 2; mt++) {
        const int r = mt * 16 + g;
        const int col = h * 64 + w * 8 + 2 * ti;
        *(__half2*)(O + (size_t)(b * Nq + n0 + r) * Cd + col) =
            __floats2half2_rn(o2[mt][0], o2[mt][1]);
        *(__half2*)(O + (size_t)(b * Nq + n0 + r + 8) * Cd + col) =
            __floats2half2_rn(o2[mt][2], o2[mt][3]);
    }
}

// ---------------------------------------------------------------------------
// Launch
// ---------------------------------------------------------------------------
extern "C" void kernel_launch(void* const* d_in, const int* in_sizes, int n_in,
                              void* d_out, int out_size) {
    const float* query   = (const float*)d_in[0];
    const float* context = (const float*)d_in[1];
    const int*   mask    = (const int*)d_in[2];
    const float* Wq      = (const float*)d_in[3];
    const float* Wk      = (const float*)d_in[4];
    const float* Wv      = (const float*)d_in[5];
    const float* qg      = (const float*)d_in[6];
    const float* qb      = (const float*)d_in[7];
    const float* kg      = (const float*)d_in[8];
    const float* kb      = (const float*)d_in[9];
    const float* Wp      = (const float*)d_in[10];
    const float* bp      = (const float*)d_in[11];

    float* out  = (float*)d_out;
    float* attn = out + (size_t)Bz * Nq * Cd;

    __half *hQ, *hK, *hV, *hO, *hq, *hc, *w0, *w1, *w2, *w3;
    cudaGetSymbolAddress((void**)&hQ, g_hQ);
    cudaGetSymbolAddress((void**)&hK, g_hK);
    cudaGetSymbolAddress((void**)&hV, g_hV);
    cudaGetSymbolAddress((void**)&hO, g_hO);
    cudaGetSymbolAddress((void**)&hq, g_hq);
    cudaGetSymbolAddress((void**)&hc, g_hc);
    cudaGetSymbolAddress((void**)&w0, g_w0);
    cudaGetSymbolAddress((void**)&w1, g_w1);
    cudaGetSymbolAddress((void**)&w2, g_w2);
    cudaGetSymbolAddress((void**)&w3, g_w3);

    cudaFuncSetAttribute(gemm_f16_mma,
                         cudaFuncAttributeMaxDynamicSharedMemorySize, GEMM_SMEM);
    cudaFuncSetAttribute(attention_kernel,
                         cudaFuncAttributeMaxDynamicSharedMemorySize, ATT_SMEM);

    // merged fp16 pre-conversion (one launch)
    cvt_all_kernel<<<(CVT_TOTAL + 255) / 256, 256>>>(
        query, context, Wq, Wk, Wv, Wp, hq, hc, w0, w1, w2, w3);

    // Projections: Q,K with fused LayerNorm -> fp16; V -> fp16
    {
        dim3 gq(Cd / 128, (Bz * Nq) / 128);
        gemm_f16_mma<<<gq, 256, GEMM_SMEM>>>(hq, w0, nullptr, nullptr, hQ, qg, qb, Cd, Cd);
        dim3 gk(Cd / 128, (Bz * Mc) / 128);
        gemm_f16_mma<<<gk, 256, GEMM_SMEM>>>(hc, w1, nullptr, nullptr, hK, kg, kb, Cd, Cd);
        gemm_f16_mma<<<gk, 256, GEMM_SMEM>>>(hc, w2, nullptr, nullptr, hV, nullptr, nullptr, Cd, Cd);
    }

    // Fused attention
    {
        dim3 ga(Nq / 32, Bz * Hh);
        attention_kernel<<<ga, 256, ATT_SMEM>>>(hQ, hK, hV, mask, attn, hO);
    }

    // Output projection + bias (fp32 out)
    {
        dim3 go(Cd / 128, (Bz * Nq) / 128);
        gemm_f16_mma<<<go, 256, GEMM_SMEM>>>(hO, w3, bp, out, nullptr, nullptr, nullptr, Cd, Cd);
    }
}